// round 1
// baseline (speedup 1.0000x reference)
#include <cuda_runtime.h>
#include <cuda_bf16.h>
#include <math.h>

// Problem constants (shapes fixed by the dataset)
#define BATCH 8
#define NPTS  8192
#define DIM   256
#define DOUT  512
#define MPTS  2048
#define KNN   16
#define RTOT  (BATCH * NPTS)   // 65536 rows
#define EPS   1e-5f

// ---------------------------------------------------------------------------
// Scratch (static __device__ arrays: no allocation at kernel_launch time)
// ---------------------------------------------------------------------------
__device__ float d_h1  [(size_t)RTOT * DIM];
__device__ float d_h2  [(size_t)RTOT * DIM];
__device__ float d_hpos[(size_t)RTOT * DIM];
__device__ float d_hgeo[(size_t)RTOT * DIM];
__device__ float d_q   [(size_t)RTOT * DIM];
__device__ float d_k   [(size_t)RTOT * DIM];
__device__ float d_v   [(size_t)RTOT * DIM];
__device__ float d_s   [(size_t)RTOT * DIM];
__device__ float d_pre [(size_t)RTOT * DIM];
__device__ float d_f   [(size_t)RTOT * DIM];
__device__ float d_g512[(size_t)RTOT * DOUT];

// ---------------------------------------------------------------------------
// GEMM: C[R x Nout] = A[R x 256] @ W[256 x Nout]  (+ epilogue)
// modes: 0 = +bias[c] + Add[r,c]   1 = *scale   2 = none
//        3 = relu(bn(acc + bias))
// 128x128 tile, BK=8, 256 threads, 8x8 per-thread register tile.
// ---------------------------------------------------------------------------
__global__ __launch_bounds__(256) void sgemm_k256(
    const float* __restrict__ A, const float* __restrict__ W,
    const float* __restrict__ bias, const float* __restrict__ Add,
    float* __restrict__ C, int Nout, int mode, float scale,
    const float* __restrict__ bn_g, const float* __restrict__ bn_b,
    const float* __restrict__ bn_mean, const float* __restrict__ bn_var)
{
    __shared__ float As[8][128];
    __shared__ float Bs[8][128];

    const int tid  = threadIdx.x;
    const int tx   = tid & 15;        // 0..15  -> col group
    const int ty   = tid >> 4;        // 0..15  -> row group
    const int arow = tid >> 1;        // 0..127
    const int acol = (tid & 1) * 4;   // 0 or 4
    const int brow = tid >> 5;        // 0..7
    const int bcol = (tid & 31) * 4;  // 0..124

    const int blockRow = blockIdx.y * 128;
    const int blockCol = blockIdx.x * 128;

    const float* Aptr = A + (size_t)(blockRow + arow) * 256 + acol;
    const float* Wptr = W + (size_t)brow * Nout + blockCol + bcol;

    float acc[8][8];
#pragma unroll
    for (int i = 0; i < 8; i++)
#pragma unroll
        for (int j = 0; j < 8; j++) acc[i][j] = 0.f;

    for (int kk = 0; kk < 256; kk += 8) {
        float4 a = *(const float4*)(Aptr + kk);
        As[acol + 0][arow] = a.x;
        As[acol + 1][arow] = a.y;
        As[acol + 2][arow] = a.z;
        As[acol + 3][arow] = a.w;
        float4 b = *(const float4*)(Wptr + (size_t)kk * Nout);
        *(float4*)&Bs[brow][bcol] = b;
        __syncthreads();
#pragma unroll
        for (int k = 0; k < 8; k++) {
            float ra[8], rb[8];
#pragma unroll
            for (int i = 0; i < 8; i++) ra[i] = As[k][ty * 8 + i];
#pragma unroll
            for (int j = 0; j < 8; j++) rb[j] = Bs[k][tx * 8 + j];
#pragma unroll
            for (int i = 0; i < 8; i++)
#pragma unroll
                for (int j = 0; j < 8; j++) acc[i][j] += ra[i] * rb[j];
        }
        __syncthreads();
    }

    const int crow0 = blockRow + ty * 8;
    const int ccol0 = blockCol + tx * 8;
#pragma unroll
    for (int i = 0; i < 8; i++) {
        size_t rowoff = (size_t)(crow0 + i) * Nout;
#pragma unroll
        for (int jj = 0; jj < 8; jj += 4) {
            float4 out;
            float* po = &out.x;
#pragma unroll
            for (int e = 0; e < 4; e++) {
                int c = ccol0 + jj + e;
                float aval = acc[i][jj + e];
                float r;
                if (mode == 0) {
                    r = aval + bias[c] + Add[rowoff + c];
                } else if (mode == 1) {
                    r = aval * scale;
                } else if (mode == 2) {
                    r = aval;
                } else {
                    float t = (aval + bias[c] - bn_mean[c]) *
                              rsqrtf(bn_var[c] + EPS) * bn_g[c] + bn_b[c];
                    r = fmaxf(t, 0.f);
                }
                po[e] = r;
            }
            *(float4*)&C[rowoff + ccol0 + jj] = out;
        }
    }
}

// ---------------------------------------------------------------------------
// Per-chunk geometry + first MLP layers (4->256 and 6->256, relu)
// One CTA per chunk of cs points; 256 threads = 256 output dims.
// ---------------------------------------------------------------------------
__global__ __launch_bounds__(256) void geom_hidden_kernel(
    const float* __restrict__ pos,
    const float* __restrict__ w1, const float* __restrict__ b1,   // (4,256),(256)
    const float* __restrict__ w2, const float* __restrict__ b2,   // (6,256),(256)
    float* __restrict__ H1, float* __restrict__ H2, int cs)
{
    __shared__ float ps[64][3];
    __shared__ float lp[64][4];
    __shared__ float cog[3], avg[3];

    const int tid = threadIdx.x;
    const size_t gp = (size_t)blockIdx.x * cs;

    if (tid < cs) {
        ps[tid][0] = pos[(gp + tid) * 3 + 0];
        ps[tid][1] = pos[(gp + tid) * 3 + 1];
        ps[tid][2] = pos[(gp + tid) * 3 + 2];
    }
    __syncthreads();
    if (tid < 3) {
        float s = 0.f;
        for (int p = 0; p < cs; p++) s += ps[p][tid];
        cog[tid] = s / (float)cs;
    }
    __syncthreads();
    if (tid < cs) {
        float x = ps[tid][0] - cog[0];
        float y = ps[tid][1] - cog[1];
        float z = ps[tid][2] - cog[2];
        lp[tid][0] = x; lp[tid][1] = y; lp[tid][2] = z;
        lp[tid][3] = sqrtf(x * x + y * y + z * z);
    }
    __syncthreads();
    if (tid < 3) {
        float s = 0.f;
        for (int p = 0; p < cs; p++) s += lp[p][tid];
        avg[tid] = s / (float)cs;
    }
    __syncthreads();

    const int j = tid;
    float w1c[4], w2c[6];
#pragma unroll
    for (int t = 0; t < 4; t++) w1c[t] = w1[t * 256 + j];
#pragma unroll
    for (int t = 0; t < 6; t++) w2c[t] = w2[t * 256 + j];
    const float b1v = b1[j], b2v = b2[j];
    const float a0 = avg[0], a1 = avg[1], a2 = avg[2];

    for (int p = 0; p < cs; p++) {
        float x = lp[p][0], y = lp[p][1], z = lp[p][2], n = lp[p][3];
        float h1 = fmaxf(b1v + x * w1c[0] + y * w1c[1] + z * w1c[2] + n * w1c[3], 0.f);
        float h2 = fmaxf(b2v + a0 * w2c[0] + a1 * w2c[1] + a2 * w2c[2] +
                               x * w2c[3] + y * w2c[4] + z * w2c[5], 0.f);
        H1[(gp + p) * 256 + j] = h1;
        H2[(gp + p) * 256 + j] = h2;
    }
}

// ---------------------------------------------------------------------------
// Per-chunk attention: S = softmax(Q K^T), out = S V.  Q prescaled by 1/16.
// smem rows padded to 257 floats to avoid 32-way bank conflicts.
// ---------------------------------------------------------------------------
__global__ __launch_bounds__(256) void attn_kernel(
    const float* __restrict__ Q, const float* __restrict__ Kf,
    const float* __restrict__ V, float* __restrict__ Out, int cs)
{
    extern __shared__ float sm[];
    float* Ks = sm;                    // cs * 257
    float* Qs = sm + (size_t)cs * 257; // cs * 257 (later reused for V)
    float* P  = sm + (size_t)2 * cs * 257; // cs * cs

    const int tid = threadIdx.x;
    const size_t base = (size_t)blockIdx.x * cs * 256;

    for (int idx = tid; idx < cs * 256; idx += 256) {
        int p = idx >> 8, t = idx & 255;
        Ks[p * 257 + t] = Kf[base + idx];
        Qs[p * 257 + t] = Q[base + idx];
    }
    __syncthreads();

    const int npair = cs * cs;
    for (int pidx = tid; pidx < npair; pidx += 256) {
        int i = pidx / cs, j = pidx % cs;
        const float* qr = &Qs[i * 257];
        const float* kr = &Ks[j * 257];
        float s = 0.f;
#pragma unroll 8
        for (int t = 0; t < 256; t++) s += qr[t] * kr[t];
        P[pidx] = s;
    }
    __syncthreads();

    const int warp = tid >> 5, lane = tid & 31;
    for (int i = warp; i < cs; i += 8) {
        float mx = -1e30f;
        for (int j = lane; j < cs; j += 32) mx = fmaxf(mx, P[i * cs + j]);
#pragma unroll
        for (int o = 16; o; o >>= 1) mx = fmaxf(mx, __shfl_xor_sync(0xFFFFFFFFu, mx, o));
        float sum = 0.f;
        for (int j = lane; j < cs; j += 32) {
            float e = __expf(P[i * cs + j] - mx);
            P[i * cs + j] = e;
            sum += e;
        }
#pragma unroll
        for (int o = 16; o; o >>= 1) sum += __shfl_xor_sync(0xFFFFFFFFu, sum, o);
        float inv = 1.f / sum;
        for (int j = lane; j < cs; j += 32) P[i * cs + j] *= inv;
    }
    __syncthreads();

    // reuse Qs for V
    for (int idx = tid; idx < cs * 256; idx += 256) {
        int p = idx >> 8, t = idx & 255;
        Qs[p * 257 + t] = V[base + idx];
    }
    __syncthreads();

    for (int idx = tid; idx < cs * 256; idx += 256) {
        int i = idx >> 8, t = idx & 255;
        float s = 0.f;
        for (int j = 0; j < cs; j++) s += P[i * cs + j] * Qs[j * 257 + t];
        Out[base + idx] = s;
    }
}

// ---------------------------------------------------------------------------
// LayerNorm over last dim (256), one CTA per row.
// ---------------------------------------------------------------------------
__global__ __launch_bounds__(256) void ln_kernel(
    const float* __restrict__ X, const float* __restrict__ g,
    const float* __restrict__ b, float* __restrict__ Y)
{
    const int row = blockIdx.x;
    const int tid = threadIdx.x;
    const int lane = tid & 31, warp = tid >> 5;
    __shared__ float red[8];
    __shared__ float smu, svar;

    float x = X[(size_t)row * 256 + tid];

    float s = x;
#pragma unroll
    for (int o = 16; o; o >>= 1) s += __shfl_xor_sync(0xFFFFFFFFu, s, o);
    if (lane == 0) red[warp] = s;
    __syncthreads();
    if (tid == 0) {
        float t = 0.f;
        for (int w = 0; w < 8; w++) t += red[w];
        smu = t / 256.f;
    }
    __syncthreads();
    float mu = smu;
    float d = x - mu;
    float s2 = d * d;
#pragma unroll
    for (int o = 16; o; o >>= 1) s2 += __shfl_xor_sync(0xFFFFFFFFu, s2, o);
    if (lane == 0) red[warp] = s2;
    __syncthreads();
    if (tid == 0) {
        float t = 0.f;
        for (int w = 0; w < 8; w++) t += red[w];
        svar = t / 256.f;
    }
    __syncthreads();
    Y[(size_t)row * 256 + tid] = d * rsqrtf(svar + EPS) * g[tid] + b[tid];
}

// ---------------------------------------------------------------------------
// kNN gather + channel max over 16 neighbors (512 channels)
// ---------------------------------------------------------------------------
__global__ __launch_bounds__(128) void knn_max_kernel(
    const float* __restrict__ G, const int* __restrict__ knn,
    float* __restrict__ out)
{
    const int bm = blockIdx.x;             // 0 .. B*M-1
    const int b  = bm / MPTS;
    const int tid = threadIdx.x;
    __shared__ int idxs[KNN];
    if (tid < KNN) idxs[tid] = knn[(size_t)bm * KNN + tid];
    __syncthreads();
    for (int c = tid; c < DOUT; c += 128) {
        float m = -3.0e38f;
#pragma unroll
        for (int k = 0; k < KNN; k++) {
            m = fmaxf(m, G[((size_t)b * NPTS + idxs[k]) * DOUT + c]);
        }
        out[(size_t)bm * DOUT + c] = m;
    }
}

__global__ void posds_kernel(const float* __restrict__ pos,
                             const int* __restrict__ fps,
                             float* __restrict__ out)
{
    int p = blockIdx.x * blockDim.x + threadIdx.x;
    if (p < BATCH * MPTS) {
        int b = p / MPTS;
        int n = fps[p];
        size_t src = ((size_t)b * NPTS + n) * 3;
        out[p * 3 + 0] = pos[src + 0];
        out[p * 3 + 1] = pos[src + 1];
        out[p * 3 + 2] = pos[src + 2];
    }
}

// ---------------------------------------------------------------------------
// Orchestration
// ---------------------------------------------------------------------------
extern "C" void kernel_launch(void* const* d_in, const int* in_sizes, int n_in,
                              void* d_out, int out_size)
{
    // cs1/cs2 may or may not appear as scalar inputs; weights start after them.
    const int s = (n_in >= 27) ? 6 : 4;

    const float* pos     = (const float*)d_in[0];
    const float* feat    = (const float*)d_in[1];
    const int*   fps     = (const int*)  d_in[2];
    const int*   knn     = (const int*)  d_in[3];
    const float* mlp1_w1 = (const float*)d_in[s + 0];
    const float* mlp1_b1 = (const float*)d_in[s + 1];
    const float* mlp1_w2 = (const float*)d_in[s + 2];
    const float* mlp1_b2 = (const float*)d_in[s + 3];
    const float* mlp2_w1 = (const float*)d_in[s + 4];
    const float* mlp2_b1 = (const float*)d_in[s + 5];
    const float* mlp2_w2 = (const float*)d_in[s + 6];
    const float* mlp2_b2 = (const float*)d_in[s + 7];
    const float* wq      = (const float*)d_in[s + 8];
    const float* wk      = (const float*)d_in[s + 9];
    const float* wv      = (const float*)d_in[s + 10];
    const float* wo      = (const float*)d_in[s + 11];
    const float* bo      = (const float*)d_in[s + 12];
    const float* ln_g    = (const float*)d_in[s + 13];
    const float* ln_b    = (const float*)d_in[s + 14];
    const float* td_w    = (const float*)d_in[s + 15];
    const float* td_b    = (const float*)d_in[s + 16];
    const float* bn_g    = (const float*)d_in[s + 17];
    const float* bn_b    = (const float*)d_in[s + 18];
    const float* bn_mean = (const float*)d_in[s + 19];
    const float* bn_var  = (const float*)d_in[s + 20];

    float *h1, *h2, *hpos, *hgeo, *qb, *kb, *vb, *sb, *pre, *fb, *g512;
    cudaGetSymbolAddress((void**)&h1,   d_h1);
    cudaGetSymbolAddress((void**)&h2,   d_h2);
    cudaGetSymbolAddress((void**)&hpos, d_hpos);
    cudaGetSymbolAddress((void**)&hgeo, d_hgeo);
    cudaGetSymbolAddress((void**)&qb,   d_q);
    cudaGetSymbolAddress((void**)&kb,   d_k);
    cudaGetSymbolAddress((void**)&vb,   d_v);
    cudaGetSymbolAddress((void**)&sb,   d_s);
    cudaGetSymbolAddress((void**)&pre,  d_pre);
    cudaGetSymbolAddress((void**)&fb,   d_f);
    cudaGetSymbolAddress((void**)&g512, d_g512);

    // attn smem for cs=64: (2*64*257 + 64*64)*4 = 147968 B
    cudaFuncSetAttribute(attn_kernel,
                         cudaFuncAttributeMaxDynamicSharedMemorySize, 151552);

    const dim3 gemmBlk(256);
    const dim3 grid256(DIM / 128, RTOT / 128);   // (2, 512)
    const dim3 grid512(DOUT / 128, RTOT / 128);  // (4, 512)

    for (int blk = 0; blk < 2; blk++) {
        const int cs = (blk == 0) ? 16 : 64;
        const int i  = blk;
        const float* fin = (blk == 0) ? feat : fb;
        const size_t wOff = (size_t)i * 256 * 256;
        const size_t bOff = (size_t)i * 256;

        geom_hidden_kernel<<<RTOT / cs, 256>>>(
            pos, mlp1_w1 + (size_t)i * 4 * 256, mlp1_b1 + bOff,
            mlp2_w1 + (size_t)i * 6 * 256, mlp2_b1 + bOff, h1, h2, cs);

        // h_pos = feat + relu(...)@w2 + b2
        sgemm_k256<<<grid256, gemmBlk>>>(h1, mlp1_w2 + wOff, mlp1_b2 + bOff, fin,
                                         hpos, DIM, 0, 1.f, nullptr, nullptr, nullptr, nullptr);
        // h_geo = feat + relu(...)@w2 + b2
        sgemm_k256<<<grid256, gemmBlk>>>(h2, mlp2_w2 + wOff, mlp2_b2 + bOff, fin,
                                         hgeo, DIM, 0, 1.f, nullptr, nullptr, nullptr, nullptr);
        // q = h_geo @ wq / 16
        sgemm_k256<<<grid256, gemmBlk>>>(hgeo, wq + wOff, nullptr, nullptr,
                                         qb, DIM, 1, 1.f / 16.f, nullptr, nullptr, nullptr, nullptr);
        // k = h_geo @ wk
        sgemm_k256<<<grid256, gemmBlk>>>(hgeo, wk + wOff, nullptr, nullptr,
                                         kb, DIM, 2, 1.f, nullptr, nullptr, nullptr, nullptr);
        // v = h_pos @ wv
        sgemm_k256<<<grid256, gemmBlk>>>(hpos, wv + wOff, nullptr, nullptr,
                                         vb, DIM, 2, 1.f, nullptr, nullptr, nullptr, nullptr);

        int smemB = (2 * cs * 257 + cs * cs) * 4;
        attn_kernel<<<RTOT / cs, 256, smemB>>>(qb, kb, vb, sb, cs);

        // pre = h_pos + (attn @ wo + bo)
        sgemm_k256<<<grid256, gemmBlk>>>(sb, wo + wOff, bo + bOff, hpos,
                                         pre, DIM, 0, 1.f, nullptr, nullptr, nullptr, nullptr);

        ln_kernel<<<RTOT, 256>>>(pre, ln_g + bOff, ln_b + bOff, fb);
    }

    // td + BN + relu
    sgemm_k256<<<grid512, gemmBlk>>>(fb, td_w, td_b, nullptr,
                                     g512, DOUT, 3, 1.f, bn_g, bn_b, bn_mean, bn_var);

    float* outp = (float*)d_out;
    posds_kernel<<<(BATCH * MPTS + 255) / 256, 256>>>(pos, fps, outp);
    knn_max_kernel<<<BATCH * MPTS, 128>>>(g512, knn, outp + BATCH * MPTS * 3);
}

// round 3
// speedup vs baseline: 1.4319x; 1.4319x over previous
#include <cuda_runtime.h>
#include <cuda_bf16.h>
#include <math.h>
#include <stdint.h>

// Problem constants
#define BATCH 8
#define NPTS  8192
#define DIM   256
#define DOUT  512
#define MPTS  2048
#define KNN   16
#define RTOT  (BATCH * NPTS)   // 65536 rows
#define EPS   1e-5f

// ---------------------------------------------------------------------------
// Scratch
// ---------------------------------------------------------------------------
__device__ __align__(128) float d_h1  [(size_t)RTOT * DIM];
__device__ __align__(128) float d_h2  [(size_t)RTOT * DIM];
__device__ __align__(128) float d_hpos[(size_t)RTOT * DIM];
__device__ __align__(128) float d_hgeo[(size_t)RTOT * DIM];
__device__ __align__(128) float d_q   [(size_t)RTOT * DIM];
__device__ __align__(128) float d_k   [(size_t)RTOT * DIM];
__device__ __align__(128) float d_v   [(size_t)RTOT * DIM];
__device__ __align__(128) float d_s   [(size_t)RTOT * DIM];
__device__ __align__(128) float d_pre [(size_t)RTOT * DIM];
__device__ __align__(128) float d_f   [(size_t)RTOT * DIM];
__device__ __align__(128) float d_g512[(size_t)RTOT * DOUT];
__device__ __align__(128) float d_wt  [14 * 256 * 256];

// ---------------------------------------------------------------------------
// helpers
// ---------------------------------------------------------------------------
__device__ __forceinline__ uint32_t f2tf32(float v) {
    uint32_t u;
    asm("cvt.rna.tf32.f32 %0, %1;" : "=r"(u) : "f"(v));
    return u;
}

__device__ __forceinline__ void mma_tf32(float* c, const uint32_t* a, const uint32_t* b) {
    asm volatile(
        "mma.sync.aligned.m16n8k8.row.col.f32.tf32.tf32.f32 "
        "{%0,%1,%2,%3}, {%4,%5,%6,%7}, {%8,%9}, {%0,%1,%2,%3};"
        : "+f"(c[0]), "+f"(c[1]), "+f"(c[2]), "+f"(c[3])
        : "r"(a[0]), "r"(a[1]), "r"(a[2]), "r"(a[3]), "r"(b[0]), "r"(b[1]));
}

// ---------------------------------------------------------------------------
// Weight transpose: W[256, N] -> Wt[N, 256]
// ---------------------------------------------------------------------------
__global__ __launch_bounds__(256) void transpose_w(
    const float* __restrict__ W, float* __restrict__ Wt, int N)
{
    __shared__ float t[32][33];
    const int bx = blockIdx.x * 32;
    const int by = blockIdx.y * 32;
    const int tx = threadIdx.x, ty = threadIdx.y;
#pragma unroll
    for (int i = ty; i < 32; i += 8)
        t[i][tx] = W[(size_t)(by + i) * N + bx + tx];
    __syncthreads();
#pragma unroll
    for (int i = ty; i < 32; i += 8)
        Wt[(size_t)(bx + i) * 256 + by + tx] = t[tx][i];
}

// ---------------------------------------------------------------------------
// tf32 mma.sync GEMM: C[R x Nout] = A[R x 256] @ Wt[Nout x 256]^T (+ epilogue)
// CTA tile 128x128, 256 threads (8 warps, 2x4), warp tile 64x32.
// BK=32, double-buffered smem in fragment-permuted layout.
// modes: 0 = +bias[c]+Add[r,c]  1 = *scale  2 = none  3 = relu(bn(acc+bias))
// ---------------------------------------------------------------------------
#define TCB_BYTES 32768               // one buffer: A 16KB + B 16KB
#define TC_SMEM_TOTAL (2 * TCB_BYTES) // 64KB

__global__ __launch_bounds__(256) void tc_gemm(
    const float* __restrict__ A, const float* __restrict__ Wt,
    const float* __restrict__ bias, const float* __restrict__ Add,
    float* __restrict__ C, int Nout, int mode, float scale,
    const float* __restrict__ bn_g, const float* __restrict__ bn_b,
    const float* __restrict__ bn_mean, const float* __restrict__ bn_var)
{
    extern __shared__ char smem[];
    const int tid  = threadIdx.x;
    const int lane = tid & 31;
    const int wid  = tid >> 5;
    const int wr   = wid >> 2;       // 0..1 -> 64-row slab
    const int wc   = wid & 3;        // 0..3 -> 32-col slab

    const int blockRow = blockIdx.y * 128;
    const int blockCol = blockIdx.x * 128;

    const float* Abase = A  + (size_t)blockRow * 256;
    const float* Bbase = Wt + (size_t)blockCol * 256;

    float acc[4][4][4];
#pragma unroll
    for (int i = 0; i < 4; i++)
#pragma unroll
        for (int j = 0; j < 4; j++)
#pragma unroll
            for (int e = 0; e < 4; e++) acc[i][j][e] = 0.f;

    // staging registers
    float4 stA[4], stB[4];

    // precomputed per-thread loader indices
    int l_rowA[4], l_c4[4];
#pragma unroll
    for (int i = 0; i < 4; i++) {
        int idx = tid + i * 256;
        l_rowA[i] = idx >> 3;   // 0..127 (also n for B)
        l_c4[i]   = idx & 7;    // float4 index within 32-float chunk
    }

    auto ldg_chunk = [&](int k0) {
#pragma unroll
        for (int i = 0; i < 4; i++) {
            stA[i] = *(const float4*)(Abase + (size_t)l_rowA[i] * 256 + k0 + l_c4[i] * 4);
            stB[i] = *(const float4*)(Bbase + (size_t)l_rowA[i] * 256 + k0 + l_c4[i] * 4);
        }
    };

    auto sts_chunk = [&](int s) {
        uint32_t* As = (uint32_t*)(smem + s * TCB_BYTES);
        uint32_t* Bs = As + 4096;
#pragma unroll
        for (int i = 0; i < 4; i++) {
            const int row = l_rowA[i], c4 = l_c4[i];
            const int kt = c4 >> 1, regc = c4 & 1;
            // A: fragment layout
            const int rt = row >> 4, rl = row & 15;
            const int g = rl & 7, regrow = rl >> 3;
            const float* va = &stA[i].x;
#pragma unroll
            for (int e = 0; e < 4; e++) {
                int alane = g * 4 + e;
                int areg  = regrow + (regc << 1);
                As[(kt * 8 + rt) * 128 + alane * 4 + areg] = f2tf32(va[e]);
            }
            // B: fragment layout
            const int nt = row >> 3, nl = row & 7;
            const float* vb = &stB[i].x;
#pragma unroll
            for (int e = 0; e < 4; e++) {
                int blane = nl * 4 + e;
                Bs[(kt * 16 + nt) * 64 + blane * 2 + regc] = f2tf32(vb[e]);
            }
        }
    };

    auto compute = [&](int s) {
        const uint32_t* As = (const uint32_t*)(smem + s * TCB_BYTES);
        const uint32_t* Bs = As + 4096;
#pragma unroll
        for (int kt = 0; kt < 4; kt++) {
            uint32_t aF[4][4], bF[4][2];
#pragma unroll
            for (int rt4 = 0; rt4 < 4; rt4++) {
                const uint32_t* p = As + ((kt * 8) + wr * 4 + rt4) * 128 + lane * 4;
                *(uint4*)aF[rt4] = *(const uint4*)p;
            }
#pragma unroll
            for (int nt4 = 0; nt4 < 4; nt4++) {
                const uint32_t* p = Bs + (kt * 16 + wc * 4 + nt4) * 64 + lane * 2;
                *(uint2*)bF[nt4] = *(const uint2*)p;
            }
#pragma unroll
            for (int rt4 = 0; rt4 < 4; rt4++)
#pragma unroll
                for (int nt4 = 0; nt4 < 4; nt4++)
                    mma_tf32(acc[rt4][nt4], aF[rt4], bF[nt4]);
        }
    };

    // pipeline: 8 chunks of K=32
    ldg_chunk(0);
    sts_chunk(0);
    __syncthreads();
#pragma unroll
    for (int c = 0; c < 8; c++) {
        if (c < 7) ldg_chunk((c + 1) * 32);
        compute(c & 1);
        if (c < 7) sts_chunk((c + 1) & 1);
        __syncthreads();
    }

    // epilogue
    const int g   = lane >> 2;
    const int tig = lane & 3;
#pragma unroll
    for (int rt4 = 0; rt4 < 4; rt4++) {
#pragma unroll
        for (int half = 0; half < 2; half++) {
            const int row = blockRow + wr * 64 + rt4 * 16 + g + half * 8;
            float* Crow = C + (size_t)row * Nout;
            const float* Arow = Add + (size_t)row * Nout;
#pragma unroll
            for (int nt4 = 0; nt4 < 4; nt4++) {
                const int col = blockCol + wc * 32 + nt4 * 8 + tig * 2;
                float v0 = acc[rt4][nt4][half * 2 + 0];
                float v1 = acc[rt4][nt4][half * 2 + 1];
                float2 out;
                if (mode == 0) {
                    out.x = v0 + bias[col]     + Arow[col];
                    out.y = v1 + bias[col + 1] + Arow[col + 1];
                } else if (mode == 1) {
                    out.x = v0 * scale; out.y = v1 * scale;
                } else if (mode == 2) {
                    out.x = v0; out.y = v1;
                } else {
                    float t0 = (v0 + bias[col] - bn_mean[col]) *
                               rsqrtf(bn_var[col] + EPS) * bn_g[col] + bn_b[col];
                    float t1 = (v1 + bias[col + 1] - bn_mean[col + 1]) *
                               rsqrtf(bn_var[col + 1] + EPS) * bn_g[col + 1] + bn_b[col + 1];
                    out.x = fmaxf(t0, 0.f); out.y = fmaxf(t1, 0.f);
                }
                *(float2*)(Crow + col) = out;
            }
        }
    }
}

// ---------------------------------------------------------------------------
// Per-chunk geometry + first MLP layers (4->256 and 6->256, relu)
// ---------------------------------------------------------------------------
__global__ __launch_bounds__(256) void geom_hidden_kernel(
    const float* __restrict__ pos,
    const float* __restrict__ w1, const float* __restrict__ b1,
    const float* __restrict__ w2, const float* __restrict__ b2,
    float* __restrict__ H1, float* __restrict__ H2, int cs)
{
    __shared__ float ps[64][3];
    __shared__ float lp[64][4];
    __shared__ float cog[3], avg[3];

    const int tid = threadIdx.x;
    const size_t gp = (size_t)blockIdx.x * cs;

    if (tid < cs) {
        ps[tid][0] = pos[(gp + tid) * 3 + 0];
        ps[tid][1] = pos[(gp + tid) * 3 + 1];
        ps[tid][2] = pos[(gp + tid) * 3 + 2];
    }
    __syncthreads();
    if (tid < 3) {
        float s = 0.f;
        for (int p = 0; p < cs; p++) s += ps[p][tid];
        cog[tid] = s / (float)cs;
    }
    __syncthreads();
    if (tid < cs) {
        float x = ps[tid][0] - cog[0];
        float y = ps[tid][1] - cog[1];
        float z = ps[tid][2] - cog[2];
        lp[tid][0] = x; lp[tid][1] = y; lp[tid][2] = z;
        lp[tid][3] = sqrtf(x * x + y * y + z * z);
    }
    __syncthreads();
    if (tid < 3) {
        float s = 0.f;
        for (int p = 0; p < cs; p++) s += lp[p][tid];
        avg[tid] = s / (float)cs;
    }
    __syncthreads();

    const int j = tid;
    float w1c[4], w2c[6];
#pragma unroll
    for (int t = 0; t < 4; t++) w1c[t] = w1[t * 256 + j];
#pragma unroll
    for (int t = 0; t < 6; t++) w2c[t] = w2[t * 256 + j];
    const float b1v = b1[j], b2v = b2[j];
    const float a0 = avg[0], a1 = avg[1], a2 = avg[2];

    for (int p = 0; p < cs; p++) {
        float x = lp[p][0], y = lp[p][1], z = lp[p][2], n = lp[p][3];
        float h1 = fmaxf(b1v + x * w1c[0] + y * w1c[1] + z * w1c[2] + n * w1c[3], 0.f);
        float h2 = fmaxf(b2v + a0 * w2c[0] + a1 * w2c[1] + a2 * w2c[2] +
                               x * w2c[3] + y * w2c[4] + z * w2c[5], 0.f);
        H1[(gp + p) * 256 + j] = h1;
        H2[(gp + p) * 256 + j] = h2;
    }
}

// ---------------------------------------------------------------------------
// Per-chunk attention
// ---------------------------------------------------------------------------
__global__ __launch_bounds__(256) void attn_kernel(
    const float* __restrict__ Q, const float* __restrict__ Kf,
    const float* __restrict__ V, float* __restrict__ Out, int cs)
{
    extern __shared__ float sm[];
    float* Ks = sm;
    float* Qs = sm + (size_t)cs * 257;
    float* P  = sm + (size_t)2 * cs * 257;

    const int tid = threadIdx.x;
    const size_t base = (size_t)blockIdx.x * cs * 256;

    for (int idx = tid; idx < cs * 256; idx += 256) {
        int p = idx >> 8, t = idx & 255;
        Ks[p * 257 + t] = Kf[base + idx];
        Qs[p * 257 + t] = Q[base + idx];
    }
    __syncthreads();

    const int npair = cs * cs;
    for (int pidx = tid; pidx < npair; pidx += 256) {
        int i = pidx / cs, j = pidx % cs;
        const float* qr = &Qs[i * 257];
        const float* kr = &Ks[j * 257];
        float s = 0.f;
#pragma unroll 8
        for (int t = 0; t < 256; t++) s += qr[t] * kr[t];
        P[pidx] = s;
    }
    __syncthreads();

    const int warp = tid >> 5, lane = tid & 31;
    for (int i = warp; i < cs; i += 8) {
        float mx = -1e30f;
        for (int j = lane; j < cs; j += 32) mx = fmaxf(mx, P[i * cs + j]);
#pragma unroll
        for (int o = 16; o; o >>= 1) mx = fmaxf(mx, __shfl_xor_sync(0xFFFFFFFFu, mx, o));
        float sum = 0.f;
        for (int j = lane; j < cs; j += 32) {
            float e = __expf(P[i * cs + j] - mx);
            P[i * cs + j] = e;
            sum += e;
        }
#pragma unroll
        for (int o = 16; o; o >>= 1) sum += __shfl_xor_sync(0xFFFFFFFFu, sum, o);
        float inv = 1.f / sum;
        for (int j = lane; j < cs; j += 32) P[i * cs + j] *= inv;
    }
    __syncthreads();

    for (int idx = tid; idx < cs * 256; idx += 256) {
        int p = idx >> 8, t = idx & 255;
        Qs[p * 257 + t] = V[base + idx];
    }
    __syncthreads();

    for (int idx = tid; idx < cs * 256; idx += 256) {
        int i = idx >> 8, t = idx & 255;
        float s = 0.f;
        for (int j = 0; j < cs; j++) s += P[i * cs + j] * Qs[j * 257 + t];
        Out[base + idx] = s;
    }
}

// ---------------------------------------------------------------------------
// LayerNorm over last dim (256)
// ---------------------------------------------------------------------------
__global__ __launch_bounds__(256) void ln_kernel(
    const float* __restrict__ X, const float* __restrict__ g,
    const float* __restrict__ b, float* __restrict__ Y)
{
    const int row = blockIdx.x;
    const int tid = threadIdx.x;
    const int lane = tid & 31, warp = tid >> 5;
    __shared__ float red[8];
    __shared__ float smu, svar;

    float x = X[(size_t)row * 256 + tid];

    float s = x;
#pragma unroll
    for (int o = 16; o; o >>= 1) s += __shfl_xor_sync(0xFFFFFFFFu, s, o);
    if (lane == 0) red[warp] = s;
    __syncthreads();
    if (tid == 0) {
        float t = 0.f;
        for (int w = 0; w < 8; w++) t += red[w];
        smu = t / 256.f;
    }
    __syncthreads();
    float mu = smu;
    float d = x - mu;
    float s2 = d * d;
#pragma unroll
    for (int o = 16; o; o >>= 1) s2 += __shfl_xor_sync(0xFFFFFFFFu, s2, o);
    if (lane == 0) red[warp] = s2;
    __syncthreads();
    if (tid == 0) {
        float t = 0.f;
        for (int w = 0; w < 8; w++) t += red[w];
        svar = t / 256.f;
    }
    __syncthreads();
    Y[(size_t)row * 256 + tid] = d * rsqrtf(svar + EPS) * g[tid] + b[tid];
}

// ---------------------------------------------------------------------------
// kNN gather + channel max, pos downsample
// ---------------------------------------------------------------------------
__global__ __launch_bounds__(128) void knn_max_kernel(
    const float* __restrict__ G, const int* __restrict__ knn,
    float* __restrict__ out)
{
    const int bm = blockIdx.x;
    const int b  = bm / MPTS;
    const int tid = threadIdx.x;
    __shared__ int idxs[KNN];
    if (tid < KNN) idxs[tid] = knn[(size_t)bm * KNN + tid];
    __syncthreads();
    for (int c = tid; c < DOUT; c += 128) {
        float m = -3.0e38f;
#pragma unroll
        for (int k = 0; k < KNN; k++) {
            m = fmaxf(m, G[((size_t)b * NPTS + idxs[k]) * DOUT + c]);
        }
        out[(size_t)bm * DOUT + c] = m;
    }
}

__global__ void posds_kernel(const float* __restrict__ pos,
                             const int* __restrict__ fps,
                             float* __restrict__ out)
{
    int p = blockIdx.x * blockDim.x + threadIdx.x;
    if (p < BATCH * MPTS) {
        int b = p / MPTS;
        int n = fps[p];
        size_t src = ((size_t)b * NPTS + n) * 3;
        out[p * 3 + 0] = pos[src + 0];
        out[p * 3 + 1] = pos[src + 1];
        out[p * 3 + 2] = pos[src + 2];
    }
}

// ---------------------------------------------------------------------------
// Orchestration
// ---------------------------------------------------------------------------
extern "C" void kernel_launch(void* const* d_in, const int* in_sizes, int n_in,
                              void* d_out, int out_size)
{
    const int s = (n_in >= 27) ? 6 : 4;

    const float* pos     = (const float*)d_in[0];
    const float* feat    = (const float*)d_in[1];
    const int*   fps     = (const int*)  d_in[2];
    const int*   knn     = (const int*)  d_in[3];
    const float* mlp1_w1 = (const float*)d_in[s + 0];
    const float* mlp1_b1 = (const float*)d_in[s + 1];
    const float* mlp1_w2 = (const float*)d_in[s + 2];
    const float* mlp1_b2 = (const float*)d_in[s + 3];
    const float* mlp2_w1 = (const float*)d_in[s + 4];
    const float* mlp2_b1 = (const float*)d_in[s + 5];
    const float* mlp2_w2 = (const float*)d_in[s + 6];
    const float* mlp2_b2 = (const float*)d_in[s + 7];
    const float* wq      = (const float*)d_in[s + 8];
    const float* wk      = (const float*)d_in[s + 9];
    const float* wv      = (const float*)d_in[s + 10];
    const float* wo      = (const float*)d_in[s + 11];
    const float* bo      = (const float*)d_in[s + 12];
    const float* ln_g    = (const float*)d_in[s + 13];
    const float* ln_b    = (const float*)d_in[s + 14];
    const float* td_w    = (const float*)d_in[s + 15];
    const float* td_b    = (const float*)d_in[s + 16];
    const float* bn_g    = (const float*)d_in[s + 17];
    const float* bn_b    = (const float*)d_in[s + 18];
    const float* bn_mean = (const float*)d_in[s + 19];
    const float* bn_var  = (const float*)d_in[s + 20];

    float *h1, *h2, *hpos, *hgeo, *qb, *kb, *vb, *sb, *pre, *fb, *g512, *wt;
    cudaGetSymbolAddress((void**)&h1,   d_h1);
    cudaGetSymbolAddress((void**)&h2,   d_h2);
    cudaGetSymbolAddress((void**)&hpos, d_hpos);
    cudaGetSymbolAddress((void**)&hgeo, d_hgeo);
    cudaGetSymbolAddress((void**)&qb,   d_q);
    cudaGetSymbolAddress((void**)&kb,   d_k);
    cudaGetSymbolAddress((void**)&vb,   d_v);
    cudaGetSymbolAddress((void**)&sb,   d_s);
    cudaGetSymbolAddress((void**)&pre,  d_pre);
    cudaGetSymbolAddress((void**)&fb,   d_f);
    cudaGetSymbolAddress((void**)&g512, d_g512);
    cudaGetSymbolAddress((void**)&wt,   d_wt);

    cudaFuncSetAttribute(attn_kernel,
                         cudaFuncAttributeMaxDynamicSharedMemorySize, 151552);
    cudaFuncSetAttribute(tc_gemm,
                         cudaFuncAttributeMaxDynamicSharedMemorySize, TC_SMEM_TOTAL);

    // --- transpose all weights into K-major [N,256] scratch ---
    const int SLOT = 256 * 256;
    const dim3 tb(32, 8);
    for (int i = 0; i < 2; i++) {
        const size_t wOff = (size_t)i * 256 * 256;
        transpose_w<<<dim3(8, 8), tb>>>(mlp1_w2 + wOff, wt + (i * 6 + 0) * SLOT, 256);
        transpose_w<<<dim3(8, 8), tb>>>(mlp2_w2 + wOff, wt + (i * 6 + 1) * SLOT, 256);
        transpose_w<<<dim3(8, 8), tb>>>(wq      + wOff, wt + (i * 6 + 2) * SLOT, 256);
        transpose_w<<<dim3(8, 8), tb>>>(wk      + wOff, wt + (i * 6 + 3) * SLOT, 256);
        transpose_w<<<dim3(8, 8), tb>>>(wv      + wOff, wt + (i * 6 + 4) * SLOT, 256);
        transpose_w<<<dim3(8, 8), tb>>>(wo      + wOff, wt + (i * 6 + 5) * SLOT, 256);
    }
    transpose_w<<<dim3(16, 8), tb>>>(td_w, wt + 12 * SLOT, 512);

    const dim3 gemmBlk(256);
    const dim3 grid256(2, RTOT / 128);   // Nout=256
    const dim3 grid512(4, RTOT / 128);   // Nout=512

    for (int blk = 0; blk < 2; blk++) {
        const int cs = (blk == 0) ? 16 : 64;
        const int i  = blk;
        const float* fin = (blk == 0) ? feat : fb;
        const size_t bOff = (size_t)i * 256;
        float* Wt0 = wt + (i * 6) * SLOT;

        geom_hidden_kernel<<<RTOT / cs, 256>>>(
            pos, mlp1_w1 + (size_t)i * 4 * 256, mlp1_b1 + bOff,
            mlp2_w1 + (size_t)i * 6 * 256, mlp2_b1 + bOff, h1, h2, cs);

        tc_gemm<<<grid256, gemmBlk, TC_SMEM_TOTAL>>>(h1, Wt0 + 0 * SLOT, mlp1_b2 + bOff, fin,
            hpos, DIM, 0, 1.f, nullptr, nullptr, nullptr, nullptr);
        tc_gemm<<<grid256, gemmBlk, TC_SMEM_TOTAL>>>(h2, Wt0 + 1 * SLOT, mlp2_b2 + bOff, fin,
            hgeo, DIM, 0, 1.f, nullptr, nullptr, nullptr, nullptr);
        tc_gemm<<<grid256, gemmBlk, TC_SMEM_TOTAL>>>(hgeo, Wt0 + 2 * SLOT, nullptr, feat,
            qb, DIM, 1, 1.f / 16.f, nullptr, nullptr, nullptr, nullptr);
        tc_gemm<<<grid256, gemmBlk, TC_SMEM_TOTAL>>>(hgeo, Wt0 + 3 * SLOT, nullptr, feat,
            kb, DIM, 2, 1.f, nullptr, nullptr, nullptr, nullptr);
        tc_gemm<<<grid256, gemmBlk, TC_SMEM_TOTAL>>>(hpos, Wt0 + 4 * SLOT, nullptr, feat,
            vb, DIM, 2, 1.f, nullptr, nullptr, nullptr, nullptr);

        int smemB = (2 * cs * 257 + cs * cs) * 4;
        attn_kernel<<<RTOT / cs, 256, smemB>>>(qb, kb, vb, sb, cs);

        tc_gemm<<<grid256, gemmBlk, TC_SMEM_TOTAL>>>(sb, Wt0 + 5 * SLOT, bo + bOff, hpos,
            pre, DIM, 0, 1.f, nullptr, nullptr, nullptr, nullptr);

        ln_kernel<<<RTOT, 256>>>(pre, ln_g + bOff, ln_b + bOff, fb);
    }

    tc_gemm<<<grid512, gemmBlk, TC_SMEM_TOTAL>>>(fb, wt + 12 * SLOT, td_b, feat,
        g512, DOUT, 3, 1.f, bn_g, bn_b, bn_mean, bn_var);

    float* outp = (float*)d_out;
    posds_kernel<<<(BATCH * MPTS + 255) / 256, 256>>>(pos, fps, outp);
    knn_max_kernel<<<BATCH * MPTS, 128>>>(g512, knn, outp + BATCH * MPTS * 3);
}

// round 5
// speedup vs baseline: 1.7281x; 1.2068x over previous
#include <cuda_runtime.h>
#include <cuda_bf16.h>
#include <math.h>
#include <stdint.h>

// Problem constants
#define BATCH 8
#define NPTS  8192
#define DIM   256
#define DOUT  512
#define MPTS  2048
#define KNN   16
#define RTOT  (BATCH * NPTS)   // 65536 rows
#define EPS   1e-5f

// ---------------------------------------------------------------------------
// Scratch
// ---------------------------------------------------------------------------
__device__ __align__(128) float d_h1  [(size_t)RTOT * DIM];
__device__ __align__(128) float d_h2  [(size_t)RTOT * DIM];
__device__ __align__(128) float d_hpos[(size_t)RTOT * DIM];
__device__ __align__(128) float d_hgeo[(size_t)RTOT * DIM];
__device__ __align__(128) float d_q   [(size_t)RTOT * DIM];
__device__ __align__(128) float d_k   [(size_t)RTOT * DIM];
__device__ __align__(128) float d_v   [(size_t)RTOT * DIM];
__device__ __align__(128) float d_s   [(size_t)RTOT * DIM];
__device__ __align__(128) float d_pre [(size_t)RTOT * DIM];
__device__ __align__(128) float d_f   [(size_t)RTOT * DIM];
__device__ __align__(128) float d_g512[(size_t)RTOT * DOUT];
__device__ __align__(128) float d_wt  [14 * 256 * 256];

#define SLOT (256 * 256)

// ---------------------------------------------------------------------------
// helpers
// ---------------------------------------------------------------------------
__device__ __forceinline__ uint32_t f2tf32(float v) {
    uint32_t u;
    asm("cvt.rna.tf32.f32 %0, %1;" : "=r"(u) : "f"(v));
    return u;
}

__device__ __forceinline__ void mma_tf32(float* c, const uint32_t* a, const uint32_t* b) {
    asm volatile(
        "mma.sync.aligned.m16n8k8.row.col.f32.tf32.tf32.f32 "
        "{%0,%1,%2,%3}, {%4,%5,%6,%7}, {%8,%9}, {%0,%1,%2,%3};"
        : "+f"(c[0]), "+f"(c[1]), "+f"(c[2]), "+f"(c[3])
        : "r"(a[0]), "r"(a[1]), "r"(a[2]), "r"(a[3]), "r"(b[0]), "r"(b[1]));
}

// ---------------------------------------------------------------------------
// Batched weight transpose: all 13 matrices in one launch.
// z: 0..11 -> block i = z/6, slot j = z%6 (m1w2, m2w2, wq, wk, wv, wo)
// z: 12,13 -> td_w column halves.
// ---------------------------------------------------------------------------
__global__ __launch_bounds__(256) void transpose_all(
    const float* __restrict__ m1w2, const float* __restrict__ m2w2,
    const float* __restrict__ wq, const float* __restrict__ wk,
    const float* __restrict__ wv, const float* __restrict__ wo,
    const float* __restrict__ td, float* __restrict__ wt)
{
    __shared__ float t[32][33];
    const int z = blockIdx.z;
    const float* src;
    int srcN = 256, colOff = 0;
    float* dst;
    if (z < 12) {
        const int i = z / 6, j = z % 6;
        const size_t off = (size_t)i * SLOT;
        switch (j) {
            case 0: src = m1w2 + off; break;
            case 1: src = m2w2 + off; break;
            case 2: src = wq   + off; break;
            case 3: src = wk   + off; break;
            case 4: src = wv   + off; break;
            default: src = wo  + off; break;
        }
        dst = wt + (size_t)(i * 6 + j) * SLOT;
    } else {
        src = td; srcN = 512; colOff = (z - 12) * 256;
        dst = wt + (size_t)(12 + (z - 12)) * SLOT;
    }

    const int bx = blockIdx.x * 32;   // n dim (within 256-unit)
    const int by = blockIdx.y * 32;   // k dim
    const int tx = threadIdx.x & 31, ty = threadIdx.x >> 5;
#pragma unroll
    for (int i = ty; i < 32; i += 8)
        t[i][tx] = src[(size_t)(by + i) * srcN + colOff + bx + tx];
    __syncthreads();
#pragma unroll
    for (int i = ty; i < 32; i += 8)
        dst[(size_t)(bx + i) * 256 + by + tx] = t[tx][i];
}

// ---------------------------------------------------------------------------
// tf32 mma.sync GEMM: C[R x Nout] = A[R x 256] @ Wt[Nout x 256]^T (+ epilogue)
// CTA tile 128x128, 256 threads (8 warps, 2x4), warp tile 64x32.
// modes: 0 = +bias[c]+Add[r,c]  1 = *scale  2 = none  3 = relu(bn(acc+bias))
//        4 = dual output: col<256 -> C (q, *scale), col>=256 -> C2 (k)
// ---------------------------------------------------------------------------
#define TCB_BYTES 32768               // one buffer: A 16KB + B 16KB
#define TC_SMEM_TOTAL (2 * TCB_BYTES) // 64KB

__global__ __launch_bounds__(256) void tc_gemm(
    const float* __restrict__ A, const float* __restrict__ Wt,
    const float* __restrict__ bias, const float* __restrict__ Add,
    float* __restrict__ C, float* __restrict__ C2,
    int Nout, int mode, float scale,
    const float* __restrict__ bn_g, const float* __restrict__ bn_b,
    const float* __restrict__ bn_mean, const float* __restrict__ bn_var)
{
    extern __shared__ char smem[];
    const int tid  = threadIdx.x;
    const int lane = tid & 31;
    const int wid  = tid >> 5;
    const int wr   = wid >> 2;       // 0..1 -> 64-row slab
    const int wc   = wid & 3;        // 0..3 -> 32-col slab

    const int blockRow = blockIdx.y * 128;
    const int blockCol = blockIdx.x * 128;

    const float* Abase = A  + (size_t)blockRow * 256;
    const float* Bbase = Wt + (size_t)blockCol * 256;

    float acc[4][4][4];
#pragma unroll
    for (int i = 0; i < 4; i++)
#pragma unroll
        for (int j = 0; j < 4; j++)
#pragma unroll
            for (int e = 0; e < 4; e++) acc[i][j][e] = 0.f;

    float4 stA[4], stB[4];
    int l_rowA[4], l_c4[4];
#pragma unroll
    for (int i = 0; i < 4; i++) {
        int idx = tid + i * 256;
        l_rowA[i] = idx >> 3;
        l_c4[i]   = idx & 7;
    }

    auto ldg_chunk = [&](int k0) {
#pragma unroll
        for (int i = 0; i < 4; i++) {
            stA[i] = *(const float4*)(Abase + (size_t)l_rowA[i] * 256 + k0 + l_c4[i] * 4);
            stB[i] = *(const float4*)(Bbase + (size_t)l_rowA[i] * 256 + k0 + l_c4[i] * 4);
        }
    };

    auto sts_chunk = [&](int s) {
        uint32_t* As = (uint32_t*)(smem + s * TCB_BYTES);
        uint32_t* Bs = As + 4096;
#pragma unroll
        for (int i = 0; i < 4; i++) {
            const int row = l_rowA[i], c4 = l_c4[i];
            const int kt = c4 >> 1, regc = c4 & 1;
            const int rt = row >> 4, rl = row & 15;
            const int g = rl & 7, regrow = rl >> 3;
            const float* va = &stA[i].x;
#pragma unroll
            for (int e = 0; e < 4; e++) {
                int alane = g * 4 + e;
                int areg  = regrow + (regc << 1);
                As[(kt * 8 + rt) * 128 + alane * 4 + areg] = f2tf32(va[e]);
            }
            const int nt = row >> 3, nl = row & 7;
            const float* vb = &stB[i].x;
#pragma unroll
            for (int e = 0; e < 4; e++) {
                int blane = nl * 4 + e;
                Bs[(kt * 16 + nt) * 64 + blane * 2 + regc] = f2tf32(vb[e]);
            }
        }
    };

    auto compute = [&](int s) {
        const uint32_t* As = (const uint32_t*)(smem + s * TCB_BYTES);
        const uint32_t* Bs = As + 4096;
#pragma unroll
        for (int kt = 0; kt < 4; kt++) {
            uint32_t aF[4][4], bF[4][2];
#pragma unroll
            for (int rt4 = 0; rt4 < 4; rt4++) {
                const uint32_t* p = As + ((kt * 8) + wr * 4 + rt4) * 128 + lane * 4;
                *(uint4*)aF[rt4] = *(const uint4*)p;
            }
#pragma unroll
            for (int nt4 = 0; nt4 < 4; nt4++) {
                const uint32_t* p = Bs + (kt * 16 + wc * 4 + nt4) * 64 + lane * 2;
                *(uint2*)bF[nt4] = *(const uint2*)p;
            }
#pragma unroll
            for (int rt4 = 0; rt4 < 4; rt4++)
#pragma unroll
                for (int nt4 = 0; nt4 < 4; nt4++)
                    mma_tf32(acc[rt4][nt4], aF[rt4], bF[nt4]);
        }
    };

    ldg_chunk(0);
    sts_chunk(0);
    __syncthreads();
#pragma unroll
    for (int c = 0; c < 8; c++) {
        if (c < 7) ldg_chunk((c + 1) * 32);
        compute(c & 1);
        if (c < 7) sts_chunk((c + 1) & 1);
        __syncthreads();
    }

    // epilogue
    const int g   = lane >> 2;
    const int tig = lane & 3;
#pragma unroll
    for (int rt4 = 0; rt4 < 4; rt4++) {
#pragma unroll
        for (int half = 0; half < 2; half++) {
            const int row = blockRow + wr * 64 + rt4 * 16 + g + half * 8;
            float* Crow = C + (size_t)row * Nout;
            const float* Arow = Add + (size_t)row * Nout;
#pragma unroll
            for (int nt4 = 0; nt4 < 4; nt4++) {
                const int col = blockCol + wc * 32 + nt4 * 8 + tig * 2;
                float v0 = acc[rt4][nt4][half * 2 + 0];
                float v1 = acc[rt4][nt4][half * 2 + 1];
                float2 out;
                if (mode == 0) {
                    out.x = v0 + bias[col]     + Arow[col];
                    out.y = v1 + bias[col + 1] + Arow[col + 1];
                    *(float2*)(Crow + col) = out;
                } else if (mode == 1) {
                    out.x = v0 * scale; out.y = v1 * scale;
                    *(float2*)(Crow + col) = out;
                } else if (mode == 2) {
                    out.x = v0; out.y = v1;
                    *(float2*)(Crow + col) = out;
                } else if (mode == 3) {
                    float t0 = (v0 + bias[col] - bn_mean[col]) *
                               rsqrtf(bn_var[col] + EPS) * bn_g[col] + bn_b[col];
                    float t1 = (v1 + bias[col + 1] - bn_mean[col + 1]) *
                               rsqrtf(bn_var[col + 1] + EPS) * bn_g[col + 1] + bn_b[col + 1];
                    out.x = fmaxf(t0, 0.f); out.y = fmaxf(t1, 0.f);
                    *(float2*)(Crow + col) = out;
                } else {  // mode 4: dual output q/k
                    if (col < 256) {
                        out.x = v0 * scale; out.y = v1 * scale;
                        *(float2*)(C + (size_t)row * 256 + col) = out;
                    } else {
                        out.x = v0; out.y = v1;
                        *(float2*)(C2 + (size_t)row * 256 + (col - 256)) = out;
                    }
                }
            }
        }
    }
}

// ---------------------------------------------------------------------------
// Per-chunk geometry + first MLP layers (4->256 and 6->256, relu)
// ---------------------------------------------------------------------------
__global__ __launch_bounds__(256) void geom_hidden_kernel(
    const float* __restrict__ pos,
    const float* __restrict__ w1, const float* __restrict__ b1,
    const float* __restrict__ w2, const float* __restrict__ b2,
    float* __restrict__ H1, float* __restrict__ H2, int cs)
{
    __shared__ float ps[64][3];
    __shared__ float lp[64][4];
    __shared__ float cog[3], avg[3];

    const int tid = threadIdx.x;
    const size_t gp = (size_t)blockIdx.x * cs;

    if (tid < cs) {
        ps[tid][0] = pos[(gp + tid) * 3 + 0];
        ps[tid][1] = pos[(gp + tid) * 3 + 1];
        ps[tid][2] = pos[(gp + tid) * 3 + 2];
    }
    __syncthreads();
    if (tid < 3) {
        float s = 0.f;
        for (int p = 0; p < cs; p++) s += ps[p][tid];
        cog[tid] = s / (float)cs;
    }
    __syncthreads();
    if (tid < cs) {
        float x = ps[tid][0] - cog[0];
        float y = ps[tid][1] - cog[1];
        float z = ps[tid][2] - cog[2];
        lp[tid][0] = x; lp[tid][1] = y; lp[tid][2] = z;
        lp[tid][3] = sqrtf(x * x + y * y + z * z);
    }
    __syncthreads();
    if (tid < 3) {
        float s = 0.f;
        for (int p = 0; p < cs; p++) s += lp[p][tid];
        avg[tid] = s / (float)cs;
    }
    __syncthreads();

    const int j = tid;
    float w1c[4], w2c[6];
#pragma unroll
    for (int t = 0; t < 4; t++) w1c[t] = w1[t * 256 + j];
#pragma unroll
    for (int t = 0; t < 6; t++) w2c[t] = w2[t * 256 + j];
    const float b1v = b1[j], b2v = b2[j];
    const float a0 = avg[0], a1 = avg[1], a2 = avg[2];

    for (int p = 0; p < cs; p++) {
        float x = lp[p][0], y = lp[p][1], z = lp[p][2], n = lp[p][3];
        float h1 = fmaxf(b1v + x * w1c[0] + y * w1c[1] + z * w1c[2] + n * w1c[3], 0.f);
        float h2 = fmaxf(b2v + a0 * w2c[0] + a1 * w2c[1] + a2 * w2c[2] +
                               x * w2c[3] + y * w2c[4] + z * w2c[5], 0.f);
        H1[(gp + p) * 256 + j] = h1;
        H2[(gp + p) * 256 + j] = h2;
    }
}

// ---------------------------------------------------------------------------
// Register-blocked chunk attention. CTA = 64 points (G = 64/CS chunks).
// smem: Qs[64*257], Ks[64*257], P[4096]; V overlays Qs/Ks (stride 264).
// ---------------------------------------------------------------------------
#define SQ 257
#define SVP 264
#define ATTN_SMEM ((2 * 64 * SQ + 4096) * 4)

template<int CS>
__global__ __launch_bounds__(256) void attn_kernel(
    const float* __restrict__ Q, const float* __restrict__ Kf,
    const float* __restrict__ V, float* __restrict__ Out)
{
    extern __shared__ float sm[];
    float* Qs = sm;
    float* Ks = sm + 64 * SQ;
    float* P  = sm + 2 * 64 * SQ;
    float* Vs = sm;                       // overlay (Q/K dead after QK phase)

    const int tid = threadIdx.x;
    const size_t base = (size_t)blockIdx.x * 64 * 256;

    for (int idx = tid; idx < 64 * 256; idx += 256) {
        int p = idx >> 8, t = idx & 255;
        Qs[p * SQ + t] = Q[base + idx];
        Ks[p * SQ + t] = Kf[base + idx];
    }
    __syncthreads();

    // ---- QK^T ----
    if (CS == 64) {
        const int i0 = (tid >> 4) * 4;
        const int j0 = (tid & 15) * 4;
        float acc[4][4] = {};
        for (int t = 0; t < 256; t++) {
            float qv[4], kv[4];
#pragma unroll
            for (int e = 0; e < 4; e++) qv[e] = Qs[(i0 + e) * SQ + t];
#pragma unroll
            for (int f = 0; f < 4; f++) kv[f] = Ks[(j0 + f) * SQ + t];
#pragma unroll
            for (int e = 0; e < 4; e++)
#pragma unroll
                for (int f = 0; f < 4; f++) acc[e][f] += qv[e] * kv[f];
        }
#pragma unroll
        for (int e = 0; e < 4; e++)
#pragma unroll
            for (int f = 0; f < 4; f++) P[(i0 + e) * 64 + j0 + f] = acc[e][f];
    } else { // CS == 16: thread = (chunk, row, j-quad)
        const int ch = tid >> 6;
        const int r  = (tid >> 2) & 15;
        const int j0 = (tid & 3) * 4;
        const int gi = ch * 16 + r;
        const int gj = ch * 16 + j0;
        float acc[4] = {};
        for (int t = 0; t < 256; t++) {
            float qv = Qs[gi * SQ + t];
#pragma unroll
            for (int f = 0; f < 4; f++) acc[f] += qv * Ks[(gj + f) * SQ + t];
        }
#pragma unroll
        for (int f = 0; f < 4; f++) P[ch * 256 + r * 16 + j0 + f] = acc[f];
    }
    __syncthreads();

    // ---- softmax ----
    if (CS == 64) {
        const int warp = tid >> 5, lane = tid & 31;
        for (int i = warp; i < 64; i += 8) {
            float* row = P + i * 64;
            float a = row[lane], b = row[lane + 32];
            float mx = fmaxf(a, b);
#pragma unroll
            for (int o = 16; o; o >>= 1) mx = fmaxf(mx, __shfl_xor_sync(0xFFFFFFFFu, mx, o));
            float ea = __expf(a - mx), eb = __expf(b - mx);
            float sum = ea + eb;
#pragma unroll
            for (int o = 16; o; o >>= 1) sum += __shfl_xor_sync(0xFFFFFFFFu, sum, o);
            float inv = 1.f / sum;
            row[lane] = ea * inv;
            row[lane + 32] = eb * inv;
        }
    } else {
        if (tid < 64) {
            float* row = P + (tid >> 4) * 256 + (tid & 15) * 16;
            float mx = -1e30f;
#pragma unroll
            for (int j = 0; j < 16; j++) mx = fmaxf(mx, row[j]);
            float sum = 0.f;
            float e[16];
#pragma unroll
            for (int j = 0; j < 16; j++) { e[j] = __expf(row[j] - mx); sum += e[j]; }
            float inv = 1.f / sum;
#pragma unroll
            for (int j = 0; j < 16; j++) row[j] = e[j] * inv;
        }
    }
    __syncthreads();

    // ---- load V (overlay Q/K) ----
    for (int idx = tid; idx < 64 * 256; idx += 256) {
        int p = idx >> 8, t = idx & 255;
        Vs[p * SVP + t] = V[base + idx];
    }
    __syncthreads();

    // ---- S @ V ----
    {
        const int i0 = (tid >> 4) * 4;       // 4 rows
        const int tq = tid & 15;             // t = tq + 16*m
        const int cb = i0 & ~(CS - 1);       // chunk base row
        float acc[4][16] = {};
        for (int j = 0; j < CS; j++) {
            float pv[4];
            if (CS == 64) {
#pragma unroll
                for (int e = 0; e < 4; e++) pv[e] = P[(i0 + e) * 64 + j];
            } else {
                const int chk = i0 >> 4;
#pragma unroll
                for (int e = 0; e < 4; e++) pv[e] = P[chk * 256 + (i0 + e - cb) * 16 + j];
            }
            const float* vr = Vs + (cb + j) * SVP + tq;
            float vv[16];
#pragma unroll
            for (int m = 0; m < 16; m++) vv[m] = vr[m * 16];
#pragma unroll
            for (int e = 0; e < 4; e++)
#pragma unroll
                for (int m = 0; m < 16; m++) acc[e][m] += pv[e] * vv[m];
        }
#pragma unroll
        for (int e = 0; e < 4; e++)
#pragma unroll
            for (int m = 0; m < 16; m++)
                Out[base + (size_t)(i0 + e) * 256 + tq + m * 16] = acc[e][m];
    }
}

// ---------------------------------------------------------------------------
// LayerNorm over last dim (256)
// ---------------------------------------------------------------------------
__global__ __launch_bounds__(256) void ln_kernel(
    const float* __restrict__ X, const float* __restrict__ g,
    const float* __restrict__ b, float* __restrict__ Y)
{
    const int row = blockIdx.x;
    const int tid = threadIdx.x;
    const int lane = tid & 31, warp = tid >> 5;
    __shared__ float red[8];
    __shared__ float smu, svar;

    float x = X[(size_t)row * 256 + tid];

    float s = x;
#pragma unroll
    for (int o = 16; o; o >>= 1) s += __shfl_xor_sync(0xFFFFFFFFu, s, o);
    if (lane == 0) red[warp] = s;
    __syncthreads();
    if (tid == 0) {
        float t = 0.f;
        for (int w = 0; w < 8; w++) t += red[w];
        smu = t / 256.f;
    }
    __syncthreads();
    float mu = smu;
    float d = x - mu;
    float s2 = d * d;
#pragma unroll
    for (int o = 16; o; o >>= 1) s2 += __shfl_xor_sync(0xFFFFFFFFu, s2, o);
    if (lane == 0) red[warp] = s2;
    __syncthreads();
    if (tid == 0) {
        float t = 0.f;
        for (int w = 0; w < 8; w++) t += red[w];
        svar = t / 256.f;
    }
    __syncthreads();
    Y[(size_t)row * 256 + tid] = d * rsqrtf(svar + EPS) * g[tid] + b[tid];
}

// ---------------------------------------------------------------------------
// kNN gather + channel max (float4), pos downsample
// ---------------------------------------------------------------------------
__global__ __launch_bounds__(128) void knn_max_kernel(
    const float* __restrict__ G, const int* __restrict__ knn,
    float* __restrict__ out)
{
    const int bm = blockIdx.x;
    const int b  = bm / MPTS;
    const int tid = threadIdx.x;
    __shared__ int idxs[KNN];
    if (tid < KNN) idxs[tid] = knn[(size_t)bm * KNN + tid];
    __syncthreads();
    float4 m = make_float4(-3.0e38f, -3.0e38f, -3.0e38f, -3.0e38f);
#pragma unroll
    for (int k = 0; k < KNN; k++) {
        const float4 gg = *(const float4*)&G[((size_t)b * NPTS + idxs[k]) * DOUT + tid * 4];
        m.x = fmaxf(m.x, gg.x); m.y = fmaxf(m.y, gg.y);
        m.z = fmaxf(m.z, gg.z); m.w = fmaxf(m.w, gg.w);
    }
    *(float4*)&out[(size_t)bm * DOUT + tid * 4] = m;
}

__global__ void posds_kernel(const float* __restrict__ pos,
                             const int* __restrict__ fps,
                             float* __restrict__ out)
{
    int p = blockIdx.x * blockDim.x + threadIdx.x;
    if (p < BATCH * MPTS) {
        int b = p / MPTS;
        int n = fps[p];
        size_t src = ((size_t)b * NPTS + n) * 3;
        out[p * 3 + 0] = pos[src + 0];
        out[p * 3 + 1] = pos[src + 1];
        out[p * 3 + 2] = pos[src + 2];
    }
}

// ---------------------------------------------------------------------------
// Orchestration
// ---------------------------------------------------------------------------
extern "C" void kernel_launch(void* const* d_in, const int* in_sizes, int n_in,
                              void* d_out, int out_size)
{
    const int s = (n_in >= 27) ? 6 : 4;

    const float* pos     = (const float*)d_in[0];
    const float* feat    = (const float*)d_in[1];
    const int*   fps     = (const int*)  d_in[2];
    const int*   knn     = (const int*)  d_in[3];
    const float* mlp1_w1 = (const float*)d_in[s + 0];
    const float* mlp1_b1 = (const float*)d_in[s + 1];
    const float* mlp1_w2 = (const float*)d_in[s + 2];
    const float* mlp1_b2 = (const float*)d_in[s + 3];
    const float* mlp2_w1 = (const float*)d_in[s + 4];
    const float* mlp2_b1 = (const float*)d_in[s + 5];
    const float* mlp2_w2 = (const float*)d_in[s + 6];
    const float* mlp2_b2 = (const float*)d_in[s + 7];
    const float* wq      = (const float*)d_in[s + 8];
    const float* wk      = (const float*)d_in[s + 9];
    const float* wv      = (const float*)d_in[s + 10];
    const float* wo      = (const float*)d_in[s + 11];
    const float* bo      = (const float*)d_in[s + 12];
    const float* ln_g    = (const float*)d_in[s + 13];
    const float* ln_b    = (const float*)d_in[s + 14];
    const float* td_w    = (const float*)d_in[s + 15];
    const float* td_b    = (const float*)d_in[s + 16];
    const float* bn_g    = (const float*)d_in[s + 17];
    const float* bn_b    = (const float*)d_in[s + 18];
    const float* bn_mean = (const float*)d_in[s + 19];
    const float* bn_var  = (const float*)d_in[s + 20];

    float *h1, *h2, *hpos, *hgeo, *qb, *kb, *vb, *sb, *pre, *fb, *g512, *wt;
    cudaGetSymbolAddress((void**)&h1,   d_h1);
    cudaGetSymbolAddress((void**)&h2,   d_h2);
    cudaGetSymbolAddress((void**)&hpos, d_hpos);
    cudaGetSymbolAddress((void**)&hgeo, d_hgeo);
    cudaGetSymbolAddress((void**)&qb,   d_q);
    cudaGetSymbolAddress((void**)&kb,   d_k);
    cudaGetSymbolAddress((void**)&vb,   d_v);
    cudaGetSymbolAddress((void**)&sb,   d_s);
    cudaGetSymbolAddress((void**)&pre,  d_pre);
    cudaGetSymbolAddress((void**)&fb,   d_f);
    cudaGetSymbolAddress((void**)&g512, d_g512);
    cudaGetSymbolAddress((void**)&wt,   d_wt);

    cudaFuncSetAttribute(tc_gemm,
                         cudaFuncAttributeMaxDynamicSharedMemorySize, TC_SMEM_TOTAL);
    cudaFuncSetAttribute(attn_kernel<16>,
                         cudaFuncAttributeMaxDynamicSharedMemorySize, ATTN_SMEM);
    cudaFuncSetAttribute(attn_kernel<64>,
                         cudaFuncAttributeMaxDynamicSharedMemorySize, ATTN_SMEM);

    // launch 0: all weight transposes
    transpose_all<<<dim3(8, 8, 14), 256>>>(mlp1_w2, mlp2_w2, wq, wk, wv, wo, td_w, wt);

    const dim3 gemmBlk(256);
    const dim3 grid256(2, RTOT / 128);   // Nout=256
    const dim3 grid512(4, RTOT / 128);   // Nout=512

    for (int blk = 0; blk < 2; blk++) {
        const int cs = (blk == 0) ? 16 : 64;
        const int i  = blk;
        const float* fin = (blk == 0) ? feat : fb;
        const size_t bOff = (size_t)i * 256;
        float* Wt0 = wt + (size_t)(i * 6) * SLOT;

        geom_hidden_kernel<<<RTOT / cs, 256>>>(
            pos, mlp1_w1 + (size_t)i * 4 * 256, mlp1_b1 + bOff,
            mlp2_w1 + (size_t)i * 6 * 256, mlp2_b1 + bOff, h1, h2, cs);

        tc_gemm<<<grid256, gemmBlk, TC_SMEM_TOTAL>>>(h1, Wt0 + 0 * SLOT, mlp1_b2 + bOff, fin,
            hpos, nullptr, DIM, 0, 1.f, nullptr, nullptr, nullptr, nullptr);
        tc_gemm<<<grid256, gemmBlk, TC_SMEM_TOTAL>>>(h2, Wt0 + 1 * SLOT, mlp2_b2 + bOff, fin,
            hgeo, nullptr, DIM, 0, 1.f, nullptr, nullptr, nullptr, nullptr);
        // fused q|k: Nout=512, cols 0-255 -> qb (*1/16), 256-511 -> kb
        tc_gemm<<<grid512, gemmBlk, TC_SMEM_TOTAL>>>(hgeo, Wt0 + 2 * SLOT, nullptr, feat,
            qb, kb, DOUT, 4, 1.f / 16.f, nullptr, nullptr, nullptr, nullptr);
        tc_gemm<<<grid256, gemmBlk, TC_SMEM_TOTAL>>>(hpos, Wt0 + 4 * SLOT, nullptr, feat,
            vb, nullptr, DIM, 2, 1.f, nullptr, nullptr, nullptr, nullptr);

        if (cs == 16)
            attn_kernel<16><<<RTOT / 64, 256, ATTN_SMEM>>>(qb, kb, vb, sb);
        else
            attn_kernel<64><<<RTOT / 64, 256, ATTN_SMEM>>>(qb, kb, vb, sb);

        tc_gemm<<<grid256, gemmBlk, TC_SMEM_TOTAL>>>(sb, Wt0 + 5 * SLOT, bo + bOff, hpos,
            pre, nullptr, DIM, 0, 1.f, nullptr, nullptr, nullptr, nullptr);

        ln_kernel<<<RTOT, 256>>>(pre, ln_g + bOff, ln_b + bOff, fb);
    }

    tc_gemm<<<grid512, gemmBlk, TC_SMEM_TOTAL>>>(fb, wt + 12 * SLOT, td_b, feat,
        g512, nullptr, DOUT, 3, 1.f, bn_g, bn_b, bn_mean, bn_var);

    float* outp = (float*)d_out;
    posds_kernel<<<(BATCH * MPTS + 255) / 256, 256>>>(pos, fps, outp);
    knn_max_kernel<<<BATCH * MPTS, 128>>>(g512, knn, outp + BATCH * MPTS * 3);
}

// round 6
// speedup vs baseline: 1.9973x; 1.1558x over previous
#include <cuda_runtime.h>
#include <cuda_bf16.h>
#include <math.h>
#include <stdint.h>

// Problem constants
#define BATCH 8
#define NPTS  8192
#define DIM   256
#define DOUT  512
#define MPTS  2048
#define KNN   16
#define RTOT  (BATCH * NPTS)   // 65536 rows
#define EPS   1e-5f

// ---------------------------------------------------------------------------
// Scratch
// ---------------------------------------------------------------------------
__device__ __align__(128) float d_h1  [(size_t)RTOT * DIM];
__device__ __align__(128) float d_h2  [(size_t)RTOT * DIM];
__device__ __align__(128) float d_hpos[(size_t)RTOT * DIM];
__device__ __align__(128) float d_hgeo[(size_t)RTOT * DIM];
__device__ __align__(128) float d_q   [(size_t)RTOT * DIM];
__device__ __align__(128) float d_k   [(size_t)RTOT * DIM];
__device__ __align__(128) float d_v   [(size_t)RTOT * DIM];
__device__ __align__(128) float d_s   [(size_t)RTOT * DIM];
__device__ __align__(128) float d_pre [(size_t)RTOT * DIM];
__device__ __align__(128) float d_f   [(size_t)RTOT * DIM];
__device__ __align__(128) float d_g512[(size_t)RTOT * DOUT];
__device__ __align__(128) float d_wt  [14 * 256 * 256];

#define SLOT (256 * 256)

// ---------------------------------------------------------------------------
// helpers
// ---------------------------------------------------------------------------
__device__ __forceinline__ void mma_tf32(float* c, const uint32_t* a, const uint32_t* b) {
    asm volatile(
        "mma.sync.aligned.m16n8k8.row.col.f32.tf32.tf32.f32 "
        "{%0,%1,%2,%3}, {%4,%5,%6,%7}, {%8,%9}, {%0,%1,%2,%3};"
        : "+f"(c[0]), "+f"(c[1]), "+f"(c[2]), "+f"(c[3])
        : "r"(a[0]), "r"(a[1]), "r"(a[2]), "r"(a[3]), "r"(b[0]), "r"(b[1]));
}

__device__ __forceinline__ uint32_t smem_u32(const void* p) {
    uint32_t a;
    asm("{ .reg .u64 t; cvta.to.shared.u64 t, %1; cvt.u32.u64 %0, t; }" : "=r"(a) : "l"(p));
    return a;
}

#define CP_ASYNC16(dst, src) \
    asm volatile("cp.async.cg.shared.global [%0], [%1], 16;" :: "r"(dst), "l"(src))
#define CP_COMMIT() asm volatile("cp.async.commit_group;")
template<int N> __device__ __forceinline__ void cp_wait() {
    asm volatile("cp.async.wait_group %0;" :: "n"(N));
}

// ---------------------------------------------------------------------------
// Batched weight transpose: all 13 matrices in one launch.
// ---------------------------------------------------------------------------
__global__ __launch_bounds__(256) void transpose_all(
    const float* __restrict__ m1w2, const float* __restrict__ m2w2,
    const float* __restrict__ wq, const float* __restrict__ wk,
    const float* __restrict__ wv, const float* __restrict__ wo,
    const float* __restrict__ td, float* __restrict__ wt)
{
    __shared__ float t[32][33];
    const int z = blockIdx.z;
    const float* src;
    int srcN = 256, colOff = 0;
    float* dst;
    if (z < 12) {
        const int i = z / 6, j = z % 6;
        const size_t off = (size_t)i * SLOT;
        switch (j) {
            case 0: src = m1w2 + off; break;
            case 1: src = m2w2 + off; break;
            case 2: src = wq   + off; break;
            case 3: src = wk   + off; break;
            case 4: src = wv   + off; break;
            default: src = wo  + off; break;
        }
        dst = wt + (size_t)(i * 6 + j) * SLOT;
    } else {
        src = td; srcN = 512; colOff = (z - 12) * 256;
        dst = wt + (size_t)(12 + (z - 12)) * SLOT;
    }

    const int bx = blockIdx.x * 32;
    const int by = blockIdx.y * 32;
    const int tx = threadIdx.x & 31, ty = threadIdx.x >> 5;
#pragma unroll
    for (int i = ty; i < 32; i += 8)
        t[i][tx] = src[(size_t)(by + i) * srcN + colOff + bx + tx];
    __syncthreads();
#pragma unroll
    for (int i = ty; i < 32; i += 8)
        dst[(size_t)(bx + i) * 256 + by + tx] = t[tx][i];
}

// ---------------------------------------------------------------------------
// tf32 mma.sync GEMM with cp.async fragment-ordered staging.
// C[R x Nout] = A[R x 256] @ Wt[Nout x 256]^T (+ epilogue)
// CTA tile 128x128, 256 threads (8 warps, 2x4), warp tile 64x32.
// K chunks of 32 floats, 3-stage cp.async ring, 2 CTAs/SM.
// smem per stage: A 16KB (4 kt * 8 rt tiles of [4 reg][32 lane]) +
//                 B 16KB (4 kt * 16 nt tiles of [2 reg][32 lane])
// modes: 0 = +bias[c]+Add[r,c]  1 = *scale  2 = none  3 = relu(bn(acc+bias))
//        4 = dual output: col<256 -> C (q, *scale), col>=256 -> C2 (k)
// ---------------------------------------------------------------------------
#define STG_BYTES 32768
#define TC_SMEM_TOTAL (3 * STG_BYTES)   // 96KB

__global__ void __launch_bounds__(256, 2) tc_gemm(
    const float* __restrict__ A, const float* __restrict__ Wt,
    const float* __restrict__ bias, const float* __restrict__ Add,
    float* __restrict__ C, float* __restrict__ C2,
    int Nout, int mode, float scale,
    const float* __restrict__ bn_g, const float* __restrict__ bn_b,
    const float* __restrict__ bn_mean, const float* __restrict__ bn_var)
{
    extern __shared__ char smem[];
    const uint32_t sbase = smem_u32(smem);
    const int tid  = threadIdx.x;
    const int lane = tid & 31;
    const int wid  = tid >> 5;
    const int wr   = wid >> 2;       // 0..1 -> 64-row slab
    const int wc   = wid & 3;        // 0..3 -> 32-col slab

    const int blockRow = blockIdx.y * 128;
    const int blockCol = blockIdx.x * 128;

    const float* Abase = A  + (size_t)blockRow * 256;
    const float* Bbase = Wt + (size_t)blockCol * 256;

    // loader mapping: r = tid&127 (row for A / n for B), q0 = tid>>7
    const int rA = tid & 127;
    const int q0 = tid >> 7;
    const float* Agr = Abase + (size_t)rA * 256;
    const float* Bgr = Bbase + (size_t)rA * 256;
    // per-i smem uint offsets (q = q0 + 2i)
    uint32_t offA[4], offB[4];
#pragma unroll
    for (int i = 0; i < 4; i++) {
        const int q = q0 + 2 * i;
        offA[i] = 4u * (((q >> 1) * 8 + (rA >> 4)) * 128 +
                        (((rA >> 3) & 1) + 2 * (q & 1)) * 32 + (rA & 7) * 4);
        offB[i] = 4u * (((q >> 1) * 16 + (rA >> 3)) * 64 +
                        (q & 1) * 32 + (rA & 7) * 4);
    }

    auto issue_chunk = [&](int c, int s) {
        const int k0 = c * 32;
        const uint32_t ab = sbase + (uint32_t)s * STG_BYTES;
        const uint32_t bb = ab + 16384u;
#pragma unroll
        for (int i = 0; i < 4; i++) {
            const int q = q0 + 2 * i;
            CP_ASYNC16(ab + offA[i], Agr + k0 + q * 4);
            CP_ASYNC16(bb + offB[i], Bgr + k0 + q * 4);
        }
        CP_COMMIT();
    };

    float acc[4][4][4];
#pragma unroll
    for (int i = 0; i < 4; i++)
#pragma unroll
        for (int j = 0; j < 4; j++)
#pragma unroll
            for (int e = 0; e < 4; e++) acc[i][j][e] = 0.f;

    auto compute = [&](int s) {
        const uint32_t* As = (const uint32_t*)(smem + s * STG_BYTES);
        const uint32_t* Bs = As + 4096;
#pragma unroll
        for (int kt = 0; kt < 4; kt++) {
            uint32_t aF[4][4], bF[4][2];
#pragma unroll
            for (int rt4 = 0; rt4 < 4; rt4++) {
                const uint32_t* p = As + (kt * 8 + wr * 4 + rt4) * 128 + lane;
#pragma unroll
                for (int r = 0; r < 4; r++) aF[rt4][r] = p[r * 32];
            }
#pragma unroll
            for (int nt4 = 0; nt4 < 4; nt4++) {
                const uint32_t* p = Bs + (kt * 16 + wc * 4 + nt4) * 64 + lane;
#pragma unroll
                for (int r = 0; r < 2; r++) bF[nt4][r] = p[r * 32];
            }
#pragma unroll
            for (int rt4 = 0; rt4 < 4; rt4++)
#pragma unroll
                for (int nt4 = 0; nt4 < 4; nt4++)
                    mma_tf32(acc[rt4][nt4], aF[rt4], bF[nt4]);
        }
    };

    issue_chunk(0, 0);
    issue_chunk(1, 1);
#pragma unroll
    for (int c = 0; c < 8; c++) {
        if (c == 7) cp_wait<0>(); else cp_wait<1>();
        __syncthreads();
        if (c + 2 < 8) issue_chunk(c + 2, (c + 2) % 3);
        compute(c % 3);
    }

    // epilogue
    const int g   = lane >> 2;
    const int tig = lane & 3;
#pragma unroll
    for (int rt4 = 0; rt4 < 4; rt4++) {
#pragma unroll
        for (int half = 0; half < 2; half++) {
            const int row = blockRow + wr * 64 + rt4 * 16 + g + half * 8;
            float* Crow = C + (size_t)row * Nout;
            const float* Arow = Add + (size_t)row * Nout;
#pragma unroll
            for (int nt4 = 0; nt4 < 4; nt4++) {
                const int col = blockCol + wc * 32 + nt4 * 8 + tig * 2;
                float v0 = acc[rt4][nt4][half * 2 + 0];
                float v1 = acc[rt4][nt4][half * 2 + 1];
                float2 out;
                if (mode == 0) {
                    out.x = v0 + bias[col]     + Arow[col];
                    out.y = v1 + bias[col + 1] + Arow[col + 1];
                    *(float2*)(Crow + col) = out;
                } else if (mode == 1) {
                    out.x = v0 * scale; out.y = v1 * scale;
                    *(float2*)(Crow + col) = out;
                } else if (mode == 2) {
                    out.x = v0; out.y = v1;
                    *(float2*)(Crow + col) = out;
                } else if (mode == 3) {
                    float t0 = (v0 + bias[col] - bn_mean[col]) *
                               rsqrtf(bn_var[col] + EPS) * bn_g[col] + bn_b[col];
                    float t1 = (v1 + bias[col + 1] - bn_mean[col + 1]) *
                               rsqrtf(bn_var[col + 1] + EPS) * bn_g[col + 1] + bn_b[col + 1];
                    out.x = fmaxf(t0, 0.f); out.y = fmaxf(t1, 0.f);
                    *(float2*)(Crow + col) = out;
                } else {  // mode 4: dual output q/k
                    if (col < 256) {
                        out.x = v0 * scale; out.y = v1 * scale;
                        *(float2*)(C + (size_t)row * 256 + col) = out;
                    } else {
                        out.x = v0; out.y = v1;
                        *(float2*)(C2 + (size_t)row * 256 + (col - 256)) = out;
                    }
                }
            }
        }
    }
}

// ---------------------------------------------------------------------------
// Per-chunk geometry + first MLP layers (4->256 and 6->256, relu)
// ---------------------------------------------------------------------------
__global__ __launch_bounds__(256) void geom_hidden_kernel(
    const float* __restrict__ pos,
    const float* __restrict__ w1, const float* __restrict__ b1,
    const float* __restrict__ w2, const float* __restrict__ b2,
    float* __restrict__ H1, float* __restrict__ H2, int cs)
{
    __shared__ float ps[64][3];
    __shared__ float lp[64][4];
    __shared__ float cog[3], avg[3];

    const int tid = threadIdx.x;
    const size_t gp = (size_t)blockIdx.x * cs;

    if (tid < cs) {
        ps[tid][0] = pos[(gp + tid) * 3 + 0];
        ps[tid][1] = pos[(gp + tid) * 3 + 1];
        ps[tid][2] = pos[(gp + tid) * 3 + 2];
    }
    __syncthreads();
    if (tid < 3) {
        float s = 0.f;
        for (int p = 0; p < cs; p++) s += ps[p][tid];
        cog[tid] = s / (float)cs;
    }
    __syncthreads();
    if (tid < cs) {
        float x = ps[tid][0] - cog[0];
        float y = ps[tid][1] - cog[1];
        float z = ps[tid][2] - cog[2];
        lp[tid][0] = x; lp[tid][1] = y; lp[tid][2] = z;
        lp[tid][3] = sqrtf(x * x + y * y + z * z);
    }
    __syncthreads();
    if (tid < 3) {
        float s = 0.f;
        for (int p = 0; p < cs; p++) s += lp[p][tid];
        avg[tid] = s / (float)cs;
    }
    __syncthreads();

    const int j = tid;
    float w1c[4], w2c[6];
#pragma unroll
    for (int t = 0; t < 4; t++) w1c[t] = w1[t * 256 + j];
#pragma unroll
    for (int t = 0; t < 6; t++) w2c[t] = w2[t * 256 + j];
    const float b1v = b1[j], b2v = b2[j];
    const float a0 = avg[0], a1 = avg[1], a2 = avg[2];

    for (int p = 0; p < cs; p++) {
        float x = lp[p][0], y = lp[p][1], z = lp[p][2], n = lp[p][3];
        float h1 = fmaxf(b1v + x * w1c[0] + y * w1c[1] + z * w1c[2] + n * w1c[3], 0.f);
        float h2 = fmaxf(b2v + a0 * w2c[0] + a1 * w2c[1] + a2 * w2c[2] +
                               x * w2c[3] + y * w2c[4] + z * w2c[5], 0.f);
        H1[(gp + p) * 256 + j] = h1;
        H2[(gp + p) * 256 + j] = h2;
    }
}

// ---------------------------------------------------------------------------
// Register-blocked chunk attention. CTA = 64 points.
// ---------------------------------------------------------------------------
#define SQ 257
#define SVP 264
#define ATTN_SMEM ((2 * 64 * SQ + 4096) * 4)

template<int CS>
__global__ __launch_bounds__(256) void attn_kernel(
    const float* __restrict__ Q, const float* __restrict__ Kf,
    const float* __restrict__ V, float* __restrict__ Out)
{
    extern __shared__ float sm[];
    float* Qs = sm;
    float* Ks = sm + 64 * SQ;
    float* P  = sm + 2 * 64 * SQ;
    float* Vs = sm;

    const int tid = threadIdx.x;
    const size_t base = (size_t)blockIdx.x * 64 * 256;

    for (int idx = tid; idx < 64 * 256; idx += 256) {
        int p = idx >> 8, t = idx & 255;
        Qs[p * SQ + t] = Q[base + idx];
        Ks[p * SQ + t] = Kf[base + idx];
    }
    __syncthreads();

    if (CS == 64) {
        const int i0 = (tid >> 4) * 4;
        const int j0 = (tid & 15) * 4;
        float acc[4][4] = {};
        for (int t = 0; t < 256; t++) {
            float qv[4], kv[4];
#pragma unroll
            for (int e = 0; e < 4; e++) qv[e] = Qs[(i0 + e) * SQ + t];
#pragma unroll
            for (int f = 0; f < 4; f++) kv[f] = Ks[(j0 + f) * SQ + t];
#pragma unroll
            for (int e = 0; e < 4; e++)
#pragma unroll
                for (int f = 0; f < 4; f++) acc[e][f] += qv[e] * kv[f];
        }
#pragma unroll
        for (int e = 0; e < 4; e++)
#pragma unroll
            for (int f = 0; f < 4; f++) P[(i0 + e) * 64 + j0 + f] = acc[e][f];
    } else {
        const int ch = tid >> 6;
        const int r  = (tid >> 2) & 15;
        const int j0 = (tid & 3) * 4;
        const int gi = ch * 16 + r;
        const int gj = ch * 16 + j0;
        float acc[4] = {};
        for (int t = 0; t < 256; t++) {
            float qv = Qs[gi * SQ + t];
#pragma unroll
            for (int f = 0; f < 4; f++) acc[f] += qv * Ks[(gj + f) * SQ + t];
        }
#pragma unroll
        for (int f = 0; f < 4; f++) P[ch * 256 + r * 16 + j0 + f] = acc[f];
    }
    __syncthreads();

    if (CS == 64) {
        const int warp = tid >> 5, lane = tid & 31;
        for (int i = warp; i < 64; i += 8) {
            float* row = P + i * 64;
            float a = row[lane], b = row[lane + 32];
            float mx = fmaxf(a, b);
#pragma unroll
            for (int o = 16; o; o >>= 1) mx = fmaxf(mx, __shfl_xor_sync(0xFFFFFFFFu, mx, o));
            float ea = __expf(a - mx), eb = __expf(b - mx);
            float sum = ea + eb;
#pragma unroll
            for (int o = 16; o; o >>= 1) sum += __shfl_xor_sync(0xFFFFFFFFu, sum, o);
            float inv = 1.f / sum;
            row[lane] = ea * inv;
            row[lane + 32] = eb * inv;
        }
    } else {
        if (tid < 64) {
            float* row = P + (tid >> 4) * 256 + (tid & 15) * 16;
            float mx = -1e30f;
#pragma unroll
            for (int j = 0; j < 16; j++) mx = fmaxf(mx, row[j]);
            float sum = 0.f;
            float e[16];
#pragma unroll
            for (int j = 0; j < 16; j++) { e[j] = __expf(row[j] - mx); sum += e[j]; }
            float inv = 1.f / sum;
#pragma unroll
            for (int j = 0; j < 16; j++) row[j] = e[j] * inv;
        }
    }
    __syncthreads();

    for (int idx = tid; idx < 64 * 256; idx += 256) {
        int p = idx >> 8, t = idx & 255;
        Vs[p * SVP + t] = V[base + idx];
    }
    __syncthreads();

    {
        const int i0 = (tid >> 4) * 4;
        const int tq = tid & 15;
        const int cb = i0 & ~(CS - 1);
        float acc[4][16] = {};
        for (int j = 0; j < CS; j++) {
            float pv[4];
            if (CS == 64) {
#pragma unroll
                for (int e = 0; e < 4; e++) pv[e] = P[(i0 + e) * 64 + j];
            } else {
                const int chk = i0 >> 4;
#pragma unroll
                for (int e = 0; e < 4; e++) pv[e] = P[chk * 256 + (i0 + e - cb) * 16 + j];
            }
            const float* vr = Vs + (cb + j) * SVP + tq;
            float vv[16];
#pragma unroll
            for (int m = 0; m < 16; m++) vv[m] = vr[m * 16];
#pragma unroll
            for (int e = 0; e < 4; e++)
#pragma unroll
                for (int m = 0; m < 16; m++) acc[e][m] += pv[e] * vv[m];
        }
#pragma unroll
        for (int e = 0; e < 4; e++)
#pragma unroll
            for (int m = 0; m < 16; m++)
                Out[base + (size_t)(i0 + e) * 256 + tq + m * 16] = acc[e][m];
    }
}

// ---------------------------------------------------------------------------
// LayerNorm over last dim (256): warp-per-row, 8 rows per CTA.
// ---------------------------------------------------------------------------
__global__ __launch_bounds__(256) void ln_kernel(
    const float* __restrict__ X, const float* __restrict__ g,
    const float* __restrict__ b, float* __restrict__ Y)
{
    const int warp = threadIdx.x >> 5, lane = threadIdx.x & 31;
    const size_t row = (size_t)blockIdx.x * 8 + warp;
    const float4* xr = (const float4*)(X + row * 256);
    float4 x0 = xr[lane], x1 = xr[lane + 32];

    float s = x0.x + x0.y + x0.z + x0.w + x1.x + x1.y + x1.z + x1.w;
#pragma unroll
    for (int o = 16; o; o >>= 1) s += __shfl_xor_sync(0xFFFFFFFFu, s, o);
    const float mu = s * (1.f / 256.f);

    float v = 0.f;
    float d0x = x0.x - mu, d0y = x0.y - mu, d0z = x0.z - mu, d0w = x0.w - mu;
    float d1x = x1.x - mu, d1y = x1.y - mu, d1z = x1.z - mu, d1w = x1.w - mu;
    v = d0x*d0x + d0y*d0y + d0z*d0z + d0w*d0w + d1x*d1x + d1y*d1y + d1z*d1z + d1w*d1w;
#pragma unroll
    for (int o = 16; o; o >>= 1) v += __shfl_xor_sync(0xFFFFFFFFu, v, o);
    const float inv = rsqrtf(v * (1.f / 256.f) + EPS);

    const float4 g0 = *(const float4*)&g[lane * 4];
    const float4 g1 = *(const float4*)&g[(lane + 32) * 4];
    const float4 b0 = *(const float4*)&b[lane * 4];
    const float4 b1 = *(const float4*)&b[(lane + 32) * 4];
    float4 y0, y1;
    y0.x = d0x * inv * g0.x + b0.x; y0.y = d0y * inv * g0.y + b0.y;
    y0.z = d0z * inv * g0.z + b0.z; y0.w = d0w * inv * g0.w + b0.w;
    y1.x = d1x * inv * g1.x + b1.x; y1.y = d1y * inv * g1.y + b1.y;
    y1.z = d1z * inv * g1.z + b1.z; y1.w = d1w * inv * g1.w + b1.w;
    float4* yr = (float4*)(Y + row * 256);
    yr[lane] = y0; yr[lane + 32] = y1;
}

// ---------------------------------------------------------------------------
// kNN gather + channel max (float4), pos downsample
// ---------------------------------------------------------------------------
__global__ __launch_bounds__(128) void knn_max_kernel(
    const float* __restrict__ G, const int* __restrict__ knn,
    float* __restrict__ out)
{
    const int bm = blockIdx.x;
    const int b  = bm / MPTS;
    const int tid = threadIdx.x;
    __shared__ int idxs[KNN];
    if (tid < KNN) idxs[tid] = knn[(size_t)bm * KNN + tid];
    __syncthreads();
    float4 m = make_float4(-3.0e38f, -3.0e38f, -3.0e38f, -3.0e38f);
#pragma unroll
    for (int k = 0; k < KNN; k++) {
        const float4 gg = *(const float4*)&G[((size_t)b * NPTS + idxs[k]) * DOUT + tid * 4];
        m.x = fmaxf(m.x, gg.x); m.y = fmaxf(m.y, gg.y);
        m.z = fmaxf(m.z, gg.z); m.w = fmaxf(m.w, gg.w);
    }
    *(float4*)&out[(size_t)bm * DOUT + tid * 4] = m;
}

__global__ void posds_kernel(const float* __restrict__ pos,
                             const int* __restrict__ fps,
                             float* __restrict__ out)
{
    int p = blockIdx.x * blockDim.x + threadIdx.x;
    if (p < BATCH * MPTS) {
        int b = p / MPTS;
        int n = fps[p];
        size_t src = ((size_t)b * NPTS + n) * 3;
        out[p * 3 + 0] = pos[src + 0];
        out[p * 3 + 1] = pos[src + 1];
        out[p * 3 + 2] = pos[src + 2];
    }
}

// ---------------------------------------------------------------------------
// Orchestration
// ---------------------------------------------------------------------------
extern "C" void kernel_launch(void* const* d_in, const int* in_sizes, int n_in,
                              void* d_out, int out_size)
{
    const int s = (n_in >= 27) ? 6 : 4;

    const float* pos     = (const float*)d_in[0];
    const float* feat    = (const float*)d_in[1];
    const int*   fps     = (const int*)  d_in[2];
    const int*   knn     = (const int*)  d_in[3];
    const float* mlp1_w1 = (const float*)d_in[s + 0];
    const float* mlp1_b1 = (const float*)d_in[s + 1];
    const float* mlp1_w2 = (const float*)d_in[s + 2];
    const float* mlp1_b2 = (const float*)d_in[s + 3];
    const float* mlp2_w1 = (const float*)d_in[s + 4];
    const float* mlp2_b1 = (const float*)d_in[s + 5];
    const float* mlp2_w2 = (const float*)d_in[s + 6];
    const float* mlp2_b2 = (const float*)d_in[s + 7];
    const float* wq      = (const float*)d_in[s + 8];
    const float* wk      = (const float*)d_in[s + 9];
    const float* wv      = (const float*)d_in[s + 10];
    const float* wo      = (const float*)d_in[s + 11];
    const float* bo      = (const float*)d_in[s + 12];
    const float* ln_g    = (const float*)d_in[s + 13];
    const float* ln_b    = (const float*)d_in[s + 14];
    const float* td_w    = (const float*)d_in[s + 15];
    const float* td_b    = (const float*)d_in[s + 16];
    const float* bn_g    = (const float*)d_in[s + 17];
    const float* bn_b    = (const float*)d_in[s + 18];
    const float* bn_mean = (const float*)d_in[s + 19];
    const float* bn_var  = (const float*)d_in[s + 20];

    float *h1, *h2, *hpos, *hgeo, *qb, *kb, *vb, *sb, *pre, *fb, *g512, *wt;
    cudaGetSymbolAddress((void**)&h1,   d_h1);
    cudaGetSymbolAddress((void**)&h2,   d_h2);
    cudaGetSymbolAddress((void**)&hpos, d_hpos);
    cudaGetSymbolAddress((void**)&hgeo, d_hgeo);
    cudaGetSymbolAddress((void**)&qb,   d_q);
    cudaGetSymbolAddress((void**)&kb,   d_k);
    cudaGetSymbolAddress((void**)&vb,   d_v);
    cudaGetSymbolAddress((void**)&sb,   d_s);
    cudaGetSymbolAddress((void**)&pre,  d_pre);
    cudaGetSymbolAddress((void**)&fb,   d_f);
    cudaGetSymbolAddress((void**)&g512, d_g512);
    cudaGetSymbolAddress((void**)&wt,   d_wt);

    cudaFuncSetAttribute(tc_gemm,
                         cudaFuncAttributeMaxDynamicSharedMemorySize, TC_SMEM_TOTAL);
    cudaFuncSetAttribute(attn_kernel<16>,
                         cudaFuncAttributeMaxDynamicSharedMemorySize, ATTN_SMEM);
    cudaFuncSetAttribute(attn_kernel<64>,
                         cudaFuncAttributeMaxDynamicSharedMemorySize, ATTN_SMEM);

    transpose_all<<<dim3(8, 8, 14), 256>>>(mlp1_w2, mlp2_w2, wq, wk, wv, wo, td_w, wt);

    const dim3 gemmBlk(256);
    const dim3 grid256(2, RTOT / 128);
    const dim3 grid512(4, RTOT / 128);

    for (int blk = 0; blk < 2; blk++) {
        const int cs = (blk == 0) ? 16 : 64;
        const int i  = blk;
        const float* fin = (blk == 0) ? feat : fb;
        const size_t bOff = (size_t)i * 256;
        float* Wt0 = wt + (size_t)(i * 6) * SLOT;

        geom_hidden_kernel<<<RTOT / cs, 256>>>(
            pos, mlp1_w1 + (size_t)i * 4 * 256, mlp1_b1 + bOff,
            mlp2_w1 + (size_t)i * 6 * 256, mlp2_b1 + bOff, h1, h2, cs);

        tc_gemm<<<grid256, gemmBlk, TC_SMEM_TOTAL>>>(h1, Wt0 + 0 * SLOT, mlp1_b2 + bOff, fin,
            hpos, nullptr, DIM, 0, 1.f, nullptr, nullptr, nullptr, nullptr);
        tc_gemm<<<grid256, gemmBlk, TC_SMEM_TOTAL>>>(h2, Wt0 + 1 * SLOT, mlp2_b2 + bOff, fin,
            hgeo, nullptr, DIM, 0, 1.f, nullptr, nullptr, nullptr, nullptr);
        tc_gemm<<<grid512, gemmBlk, TC_SMEM_TOTAL>>>(hgeo, Wt0 + 2 * SLOT, nullptr, feat,
            qb, kb, DOUT, 4, 1.f / 16.f, nullptr, nullptr, nullptr, nullptr);
        tc_gemm<<<grid256, gemmBlk, TC_SMEM_TOTAL>>>(hpos, Wt0 + 4 * SLOT, nullptr, feat,
            vb, nullptr, DIM, 2, 1.f, nullptr, nullptr, nullptr, nullptr);

        if (cs == 16)
            attn_kernel<16><<<RTOT / 64, 256, ATTN_SMEM>>>(qb, kb, vb, sb);
        else
            attn_kernel<64><<<RTOT / 64, 256, ATTN_SMEM>>>(qb, kb, vb, sb);

        tc_gemm<<<grid256, gemmBlk, TC_SMEM_TOTAL>>>(sb, Wt0 + 5 * SLOT, bo + bOff, hpos,
            pre, nullptr, DIM, 0, 1.f, nullptr, nullptr, nullptr, nullptr);

        ln_kernel<<<RTOT / 8, 256>>>(pre, ln_g + bOff, ln_b + bOff, fb);
    }

    tc_gemm<<<grid512, gemmBlk, TC_SMEM_TOTAL>>>(fb, wt + 12 * SLOT, td_b, feat,
        g512, nullptr, DOUT, 3, 1.f, bn_g, bn_b, bn_mean, bn_var);

    float* outp = (float*)d_out;
    posds_kernel<<<(BATCH * MPTS + 255) / 256, 256>>>(pos, fps, outp);
    knn_max_kernel<<<BATCH * MPTS, 128>>>(g512, knn, outp + BATCH * MPTS * 3);
}

// round 7
// speedup vs baseline: 2.0491x; 1.0259x over previous
#include <cuda_runtime.h>
#include <cuda_bf16.h>
#include <math.h>
#include <stdint.h>

// Problem constants
#define BATCH 8
#define NPTS  8192
#define DIM   256
#define DOUT  512
#define MPTS  2048
#define KNN   16
#define RTOT  (BATCH * NPTS)   // 65536 rows
#define EPS   1e-5f

// ---------------------------------------------------------------------------
// Scratch
// ---------------------------------------------------------------------------
__device__ __align__(128) float d_h1  [(size_t)RTOT * DIM];
__device__ __align__(128) float d_h2  [(size_t)RTOT * DIM];
__device__ __align__(128) float d_hpos[(size_t)RTOT * DIM];
__device__ __align__(128) float d_hgeo[(size_t)RTOT * DIM];
__device__ __align__(128) float d_q   [(size_t)RTOT * DIM];
__device__ __align__(128) float d_k   [(size_t)RTOT * DIM];
__device__ __align__(128) float d_v   [(size_t)RTOT * DIM];
__device__ __align__(128) float d_s   [(size_t)RTOT * DIM];
__device__ __align__(128) float d_pre [(size_t)RTOT * DIM];
__device__ __align__(128) float d_f   [(size_t)RTOT * DIM];
__device__ __align__(128) float d_g512[(size_t)RTOT * DOUT];
__device__ __align__(128) float d_wt  [14 * 256 * 256];

#define SLOT (256 * 256)

// ---------------------------------------------------------------------------
// helpers
// ---------------------------------------------------------------------------
__device__ __forceinline__ float f2tf32_rn(float v) {
    uint32_t u;
    asm("cvt.rna.tf32.f32 %0, %1;" : "=r"(u) : "f"(v));
    return __uint_as_float(u);
}

__device__ __forceinline__ void mma_tf32(float* c, const uint32_t* a, const uint32_t* b) {
    asm volatile(
        "mma.sync.aligned.m16n8k8.row.col.f32.tf32.tf32.f32 "
        "{%0,%1,%2,%3}, {%4,%5,%6,%7}, {%8,%9}, {%0,%1,%2,%3};"
        : "+f"(c[0]), "+f"(c[1]), "+f"(c[2]), "+f"(c[3])
        : "r"(a[0]), "r"(a[1]), "r"(a[2]), "r"(a[3]), "r"(b[0]), "r"(b[1]));
}

__device__ __forceinline__ uint32_t smem_u32(const void* p) {
    uint32_t a;
    asm("{ .reg .u64 t; cvta.to.shared.u64 t, %1; cvt.u32.u64 %0, t; }" : "=r"(a) : "l"(p));
    return a;
}

#define CP_ASYNC16(dst, src) \
    asm volatile("cp.async.cg.shared.global [%0], [%1], 16;" :: "r"(dst), "l"(src))
#define CP_COMMIT() asm volatile("cp.async.commit_group;")
template<int N> __device__ __forceinline__ void cp_wait() {
    asm volatile("cp.async.wait_group %0;" :: "n"(N));
}

// ---------------------------------------------------------------------------
// Batched weight transpose (rounded to tf32-rn at write)
// ---------------------------------------------------------------------------
__global__ __launch_bounds__(256) void transpose_all(
    const float* __restrict__ m1w2, const float* __restrict__ m2w2,
    const float* __restrict__ wq, const float* __restrict__ wk,
    const float* __restrict__ wv, const float* __restrict__ wo,
    const float* __restrict__ td, float* __restrict__ wt)
{
    __shared__ float t[32][33];
    const int z = blockIdx.z;
    const float* src;
    int srcN = 256, colOff = 0;
    float* dst;
    if (z < 12) {
        const int i = z / 6, j = z % 6;
        const size_t off = (size_t)i * SLOT;
        switch (j) {
            case 0: src = m1w2 + off; break;
            case 1: src = m2w2 + off; break;
            case 2: src = wq   + off; break;
            case 3: src = wk   + off; break;
            case 4: src = wv   + off; break;
            default: src = wo  + off; break;
        }
        dst = wt + (size_t)(i * 6 + j) * SLOT;
    } else {
        src = td; srcN = 512; colOff = (z - 12) * 256;
        dst = wt + (size_t)(12 + (z - 12)) * SLOT;
    }

    const int bx = blockIdx.x * 32;
    const int by = blockIdx.y * 32;
    const int tx = threadIdx.x & 31, ty = threadIdx.x >> 5;
#pragma unroll
    for (int i = ty; i < 32; i += 8)
        t[i][tx] = src[(size_t)(by + i) * srcN + colOff + bx + tx];
    __syncthreads();
#pragma unroll
    for (int i = ty; i < 32; i += 8)
        dst[(size_t)(bx + i) * 256 + by + tx] = f2tf32_rn(t[tx][i]);
}

// ---------------------------------------------------------------------------
// tf32 mma.sync GEMM, cp.async fragment-ordered staging.
// CTA tile 256x128, 512 threads (16 warps, 4x4), warp tile 64x32.
// K chunks of 32 floats, 4-stage ring (48KB/stage, 192KB), 1 CTA/SM.
// modes: 0 = +bias[c]+Add[r,c]  1 = *scale  2 = none  3 = relu(bn(acc+bias))
//        4 = dual output: col<256 -> C (q, *scale), col>=256 -> C2 (k)
// ---------------------------------------------------------------------------
#define STG_BYTES 49152                 // A 32KB + B 16KB
#define TC_SMEM_TOTAL (4 * STG_BYTES)   // 192KB

__global__ void __launch_bounds__(512, 1) tc_gemm(
    const float* __restrict__ A, const float* __restrict__ Wt,
    const float* __restrict__ bias, const float* __restrict__ Add,
    float* __restrict__ C, float* __restrict__ C2,
    int Nout, int mode, float scale,
    const float* __restrict__ bn_g, const float* __restrict__ bn_b,
    const float* __restrict__ bn_mean, const float* __restrict__ bn_var)
{
    extern __shared__ char smem[];
    const uint32_t sbase = smem_u32(smem);
    const int tid  = threadIdx.x;
    const int lane = tid & 31;
    const int wid  = tid >> 5;
    const int wr   = wid >> 2;       // 0..3 -> 64-row slab
    const int wc   = wid & 3;        // 0..3 -> 32-col slab

    const int blockRow = blockIdx.y * 256;
    const int blockCol = blockIdx.x * 128;

    const float* Abase = A  + (size_t)blockRow * 256;
    const float* Bbase = Wt + (size_t)blockCol * 256;

    // A loader: 2048 float4 per chunk -> 4 per thread
    int rowA[4], qA[4];
    uint32_t offA[4];
#pragma unroll
    for (int i = 0; i < 4; i++) {
        const int idx = tid + i * 512;
        rowA[i] = idx >> 3;           // 0..255
        qA[i]   = idx & 7;
        offA[i] = 4u * (((uint32_t)(qA[i] >> 1) * 16 + (rowA[i] >> 4)) * 128 +
                        (((rowA[i] >> 3) & 1) + 2 * (qA[i] & 1)) * 32 + (rowA[i] & 7) * 4);
    }
    // B loader: 1024 float4 per chunk -> 2 per thread
    int rowB[2], qB[2];
    uint32_t offB[2];
#pragma unroll
    for (int i = 0; i < 2; i++) {
        const int idx = tid + i * 512;
        rowB[i] = idx >> 3;           // 0..127
        qB[i]   = idx & 7;
        offB[i] = 4u * (((uint32_t)(qB[i] >> 1) * 16 + (rowB[i] >> 3)) * 64 +
                        (qB[i] & 1) * 32 + (rowB[i] & 7) * 4);
    }

    auto issue_chunk = [&](int c, int s) {
        const int k0 = c * 32;
        const uint32_t ab = sbase + (uint32_t)s * STG_BYTES;
        const uint32_t bb = ab + 32768u;
#pragma unroll
        for (int i = 0; i < 4; i++)
            CP_ASYNC16(ab + offA[i], Abase + (size_t)rowA[i] * 256 + k0 + qA[i] * 4);
#pragma unroll
        for (int i = 0; i < 2; i++)
            CP_ASYNC16(bb + offB[i], Bbase + (size_t)rowB[i] * 256 + k0 + qB[i] * 4);
        CP_COMMIT();
    };

    float acc[4][4][4];
#pragma unroll
    for (int i = 0; i < 4; i++)
#pragma unroll
        for (int j = 0; j < 4; j++)
#pragma unroll
            for (int e = 0; e < 4; e++) acc[i][j][e] = 0.f;

    auto compute = [&](int s) {
        const uint32_t* As = (const uint32_t*)(smem + s * STG_BYTES);
        const uint32_t* Bs = As + 8192;
#pragma unroll
        for (int kt = 0; kt < 4; kt++) {
            uint32_t aF[4][4], bF[4][2];
#pragma unroll
            for (int rt4 = 0; rt4 < 4; rt4++) {
                const uint32_t* p = As + (kt * 16 + wr * 4 + rt4) * 128 + lane;
#pragma unroll
                for (int r = 0; r < 4; r++) aF[rt4][r] = p[r * 32];
            }
#pragma unroll
            for (int nt4 = 0; nt4 < 4; nt4++) {
                const uint32_t* p = Bs + (kt * 16 + wc * 4 + nt4) * 64 + lane;
#pragma unroll
                for (int r = 0; r < 2; r++) bF[nt4][r] = p[r * 32];
            }
#pragma unroll
            for (int rt4 = 0; rt4 < 4; rt4++)
#pragma unroll
                for (int nt4 = 0; nt4 < 4; nt4++)
                    mma_tf32(acc[rt4][nt4], aF[rt4], bF[nt4]);
        }
    };

    issue_chunk(0, 0);
    issue_chunk(1, 1);
    issue_chunk(2, 2);
#pragma unroll
    for (int c = 0; c < 8; c++) {
        if (c <= 5)      cp_wait<2>();
        else if (c == 6) cp_wait<1>();
        else             cp_wait<0>();
        __syncthreads();
        if (c + 3 < 8) issue_chunk(c + 3, (c + 3) & 3);
        compute(c & 3);
    }

    // epilogue
    const int g   = lane >> 2;
    const int tig = lane & 3;
#pragma unroll
    for (int rt4 = 0; rt4 < 4; rt4++) {
#pragma unroll
        for (int half = 0; half < 2; half++) {
            const int row = blockRow + wr * 64 + rt4 * 16 + g + half * 8;
            float* Crow = C + (size_t)row * Nout;
            const float* Arow = Add + (size_t)row * Nout;
#pragma unroll
            for (int nt4 = 0; nt4 < 4; nt4++) {
                const int col = blockCol + wc * 32 + nt4 * 8 + tig * 2;
                float v0 = acc[rt4][nt4][half * 2 + 0];
                float v1 = acc[rt4][nt4][half * 2 + 1];
                float2 out;
                if (mode == 0) {
                    out.x = v0 + bias[col]     + Arow[col];
                    out.y = v1 + bias[col + 1] + Arow[col + 1];
                    *(float2*)(Crow + col) = out;
                } else if (mode == 1) {
                    out.x = v0 * scale; out.y = v1 * scale;
                    *(float2*)(Crow + col) = out;
                } else if (mode == 2) {
                    out.x = v0; out.y = v1;
                    *(float2*)(Crow + col) = out;
                } else if (mode == 3) {
                    float t0 = (v0 + bias[col] - bn_mean[col]) *
                               rsqrtf(bn_var[col] + EPS) * bn_g[col] + bn_b[col];
                    float t1 = (v1 + bias[col + 1] - bn_mean[col + 1]) *
                               rsqrtf(bn_var[col + 1] + EPS) * bn_g[col + 1] + bn_b[col + 1];
                    out.x = fmaxf(t0, 0.f); out.y = fmaxf(t1, 0.f);
                    *(float2*)(Crow + col) = out;
                } else {  // mode 4: dual output q/k
                    if (col < 256) {
                        out.x = v0 * scale; out.y = v1 * scale;
                        *(float2*)(C + (size_t)row * 256 + col) = out;
                    } else {
                        out.x = v0; out.y = v1;
                        *(float2*)(C2 + (size_t)row * 256 + (col - 256)) = out;
                    }
                }
            }
        }
    }
}

// ---------------------------------------------------------------------------
// Per-chunk geometry + first MLP layers (4->256 and 6->256, relu)
// Outputs rounded to tf32-rn (pure GEMM-A inputs).
// ---------------------------------------------------------------------------
__global__ __launch_bounds__(256) void geom_hidden_kernel(
    const float* __restrict__ pos,
    const float* __restrict__ w1, const float* __restrict__ b1,
    const float* __restrict__ w2, const float* __restrict__ b2,
    float* __restrict__ H1, float* __restrict__ H2, int cs)
{
    __shared__ float ps[64][3];
    __shared__ float lp[64][4];
    __shared__ float cog[3], avg[3];

    const int tid = threadIdx.x;
    const size_t gp = (size_t)blockIdx.x * cs;

    if (tid < cs) {
        ps[tid][0] = pos[(gp + tid) * 3 + 0];
        ps[tid][1] = pos[(gp + tid) * 3 + 1];
        ps[tid][2] = pos[(gp + tid) * 3 + 2];
    }
    __syncthreads();
    if (tid < 3) {
        float s = 0.f;
        for (int p = 0; p < cs; p++) s += ps[p][tid];
        cog[tid] = s / (float)cs;
    }
    __syncthreads();
    if (tid < cs) {
        float x = ps[tid][0] - cog[0];
        float y = ps[tid][1] - cog[1];
        float z = ps[tid][2] - cog[2];
        lp[tid][0] = x; lp[tid][1] = y; lp[tid][2] = z;
        lp[tid][3] = sqrtf(x * x + y * y + z * z);
    }
    __syncthreads();
    if (tid < 3) {
        float s = 0.f;
        for (int p = 0; p < cs; p++) s += lp[p][tid];
        avg[tid] = s / (float)cs;
    }
    __syncthreads();

    const int j = tid;
    float w1c[4], w2c[6];
#pragma unroll
    for (int t = 0; t < 4; t++) w1c[t] = w1[t * 256 + j];
#pragma unroll
    for (int t = 0; t < 6; t++) w2c[t] = w2[t * 256 + j];
    const float b1v = b1[j], b2v = b2[j];
    const float a0 = avg[0], a1 = avg[1], a2 = avg[2];

    for (int p = 0; p < cs; p++) {
        float x = lp[p][0], y = lp[p][1], z = lp[p][2], n = lp[p][3];
        float h1 = fmaxf(b1v + x * w1c[0] + y * w1c[1] + z * w1c[2] + n * w1c[3], 0.f);
        float h2 = fmaxf(b2v + a0 * w2c[0] + a1 * w2c[1] + a2 * w2c[2] +
                               x * w2c[3] + y * w2c[4] + z * w2c[5], 0.f);
        H1[(gp + p) * 256 + j] = f2tf32_rn(h1);
        H2[(gp + p) * 256 + j] = f2tf32_rn(h2);
    }
}

// ---------------------------------------------------------------------------
// Register-blocked chunk attention. CTA = 64 points.
// Output rounded to tf32-rn (pure GEMM-A input).
// ---------------------------------------------------------------------------
#define SQ 257
#define SVP 264
#define ATTN_SMEM ((2 * 64 * SQ + 4096) * 4)

template<int CS>
__global__ __launch_bounds__(256) void attn_kernel(
    const float* __restrict__ Q, const float* __restrict__ Kf,
    const float* __restrict__ V, float* __restrict__ Out)
{
    extern __shared__ float sm[];
    float* Qs = sm;
    float* Ks = sm + 64 * SQ;
    float* P  = sm + 2 * 64 * SQ;
    float* Vs = sm;

    const int tid = threadIdx.x;
    const size_t base = (size_t)blockIdx.x * 64 * 256;

    for (int idx = tid; idx < 64 * 256; idx += 256) {
        int p = idx >> 8, t = idx & 255;
        Qs[p * SQ + t] = Q[base + idx];
        Ks[p * SQ + t] = Kf[base + idx];
    }
    __syncthreads();

    if (CS == 64) {
        const int i0 = (tid >> 4) * 4;
        const int j0 = (tid & 15) * 4;
        float acc[4][4] = {};
        for (int t = 0; t < 256; t++) {
            float qv[4], kv[4];
#pragma unroll
            for (int e = 0; e < 4; e++) qv[e] = Qs[(i0 + e) * SQ + t];
#pragma unroll
            for (int f = 0; f < 4; f++) kv[f] = Ks[(j0 + f) * SQ + t];
#pragma unroll
            for (int e = 0; e < 4; e++)
#pragma unroll
                for (int f = 0; f < 4; f++) acc[e][f] += qv[e] * kv[f];
        }
#pragma unroll
        for (int e = 0; e < 4; e++)
#pragma unroll
            for (int f = 0; f < 4; f++) P[(i0 + e) * 64 + j0 + f] = acc[e][f];
    } else {
        const int ch = tid >> 6;
        const int r  = (tid >> 2) & 15;
        const int j0 = (tid & 3) * 4;
        const int gi = ch * 16 + r;
        const int gj = ch * 16 + j0;
        float acc[4] = {};
        for (int t = 0; t < 256; t++) {
            float qv = Qs[gi * SQ + t];
#pragma unroll
            for (int f = 0; f < 4; f++) acc[f] += qv * Ks[(gj + f) * SQ + t];
        }
#pragma unroll
        for (int f = 0; f < 4; f++) P[ch * 256 + r * 16 + j0 + f] = acc[f];
    }
    __syncthreads();

    if (CS == 64) {
        const int warp = tid >> 5, lane = tid & 31;
        for (int i = warp; i < 64; i += 8) {
            float* row = P + i * 64;
            float a = row[lane], b = row[lane + 32];
            float mx = fmaxf(a, b);
#pragma unroll
            for (int o = 16; o; o >>= 1) mx = fmaxf(mx, __shfl_xor_sync(0xFFFFFFFFu, mx, o));
            float ea = __expf(a - mx), eb = __expf(b - mx);
            float sum = ea + eb;
#pragma unroll
            for (int o = 16; o; o >>= 1) sum += __shfl_xor_sync(0xFFFFFFFFu, sum, o);
            float inv = 1.f / sum;
            row[lane] = ea * inv;
            row[lane + 32] = eb * inv;
        }
    } else {
        if (tid < 64) {
            float* row = P + (tid >> 4) * 256 + (tid & 15) * 16;
            float mx = -1e30f;
#pragma unroll
            for (int j = 0; j < 16; j++) mx = fmaxf(mx, row[j]);
            float sum = 0.f;
            float e[16];
#pragma unroll
            for (int j = 0; j < 16; j++) { e[j] = __expf(row[j] - mx); sum += e[j]; }
            float inv = 1.f / sum;
#pragma unroll
            for (int j = 0; j < 16; j++) row[j] = e[j] * inv;
        }
    }
    __syncthreads();

    for (int idx = tid; idx < 64 * 256; idx += 256) {
        int p = idx >> 8, t = idx & 255;
        Vs[p * SVP + t] = V[base + idx];
    }
    __syncthreads();

    {
        const int i0 = (tid >> 4) * 4;
        const int tq = tid & 15;
        const int cb = i0 & ~(CS - 1);
        float acc[4][16] = {};
        for (int j = 0; j < CS; j++) {
            float pv[4];
            if (CS == 64) {
#pragma unroll
                for (int e = 0; e < 4; e++) pv[e] = P[(i0 + e) * 64 + j];
            } else {
                const int chk = i0 >> 4;
#pragma unroll
                for (int e = 0; e < 4; e++) pv[e] = P[chk * 256 + (i0 + e - cb) * 16 + j];
            }
            const float* vr = Vs + (cb + j) * SVP + tq;
            float vv[16];
#pragma unroll
            for (int m = 0; m < 16; m++) vv[m] = vr[m * 16];
#pragma unroll
            for (int e = 0; e < 4; e++)
#pragma unroll
                for (int m = 0; m < 16; m++) acc[e][m] += pv[e] * vv[m];
        }
#pragma unroll
        for (int e = 0; e < 4; e++)
#pragma unroll
            for (int m = 0; m < 16; m++)
                Out[base + (size_t)(i0 + e) * 256 + tq + m * 16] = f2tf32_rn(acc[e][m]);
    }
}

// ---------------------------------------------------------------------------
// LayerNorm over last dim (256): warp-per-row, 8 rows per CTA.
// ---------------------------------------------------------------------------
__global__ __launch_bounds__(256) void ln_kernel(
    const float* __restrict__ X, const float* __restrict__ g,
    const float* __restrict__ b, float* __restrict__ Y)
{
    const int warp = threadIdx.x >> 5, lane = threadIdx.x & 31;
    const size_t row = (size_t)blockIdx.x * 8 + warp;
    const float4* xr = (const float4*)(X + row * 256);
    float4 x0 = xr[lane], x1 = xr[lane + 32];

    float s = x0.x + x0.y + x0.z + x0.w + x1.x + x1.y + x1.z + x1.w;
#pragma unroll
    for (int o = 16; o; o >>= 1) s += __shfl_xor_sync(0xFFFFFFFFu, s, o);
    const float mu = s * (1.f / 256.f);

    float v = 0.f;
    float d0x = x0.x - mu, d0y = x0.y - mu, d0z = x0.z - mu, d0w = x0.w - mu;
    float d1x = x1.x - mu, d1y = x1.y - mu, d1z = x1.z - mu, d1w = x1.w - mu;
    v = d0x*d0x + d0y*d0y + d0z*d0z + d0w*d0w + d1x*d1x + d1y*d1y + d1z*d1z + d1w*d1w;
#pragma unroll
    for (int o = 16; o; o >>= 1) v += __shfl_xor_sync(0xFFFFFFFFu, v, o);
    const float inv = rsqrtf(v * (1.f / 256.f) + EPS);

    const float4 g0 = *(const float4*)&g[lane * 4];
    const float4 g1 = *(const float4*)&g[(lane + 32) * 4];
    const float4 b0 = *(const float4*)&b[lane * 4];
    const float4 b1 = *(const float4*)&b[(lane + 32) * 4];
    float4 y0, y1;
    y0.x = d0x * inv * g0.x + b0.x; y0.y = d0y * inv * g0.y + b0.y;
    y0.z = d0z * inv * g0.z + b0.z; y0.w = d0w * inv * g0.w + b0.w;
    y1.x = d1x * inv * g1.x + b1.x; y1.y = d1y * inv * g1.y + b1.y;
    y1.z = d1z * inv * g1.z + b1.z; y1.w = d1w * inv * g1.w + b1.w;
    float4* yr = (float4*)(Y + row * 256);
    yr[lane] = y0; yr[lane + 32] = y1;
}

// ---------------------------------------------------------------------------
// kNN gather + channel max (float4), pos downsample
// ---------------------------------------------------------------------------
__global__ __launch_bounds__(128) void knn_max_kernel(
    const float* __restrict__ G, const int* __restrict__ knn,
    float* __restrict__ out)
{
    const int bm = blockIdx.x;
    const int b  = bm / MPTS;
    const int tid = threadIdx.x;
    __shared__ int idxs[KNN];
    if (tid < KNN) idxs[tid] = knn[(size_t)bm * KNN + tid];
    __syncthreads();
    float4 m = make_float4(-3.0e38f, -3.0e38f, -3.0e38f, -3.0e38f);
#pragma unroll
    for (int k = 0; k < KNN; k++) {
        const float4 gg = *(const float4*)&G[((size_t)b * NPTS + idxs[k]) * DOUT + tid * 4];
        m.x = fmaxf(m.x, gg.x); m.y = fmaxf(m.y, gg.y);
        m.z = fmaxf(m.z, gg.z); m.w = fmaxf(m.w, gg.w);
    }
    *(float4*)&out[(size_t)bm * DOUT + tid * 4] = m;
}

__global__ void posds_kernel(const float* __restrict__ pos,
                             const int* __restrict__ fps,
                             float* __restrict__ out)
{
    int p = blockIdx.x * blockDim.x + threadIdx.x;
    if (p < BATCH * MPTS) {
        int b = p / MPTS;
        int n = fps[p];
        size_t src = ((size_t)b * NPTS + n) * 3;
        out[p * 3 + 0] = pos[src + 0];
        out[p * 3 + 1] = pos[src + 1];
        out[p * 3 + 2] = pos[src + 2];
    }
}

// ---------------------------------------------------------------------------
// Orchestration
// ---------------------------------------------------------------------------
extern "C" void kernel_launch(void* const* d_in, const int* in_sizes, int n_in,
                              void* d_out, int out_size)
{
    const int s = (n_in >= 27) ? 6 : 4;

    const float* pos     = (const float*)d_in[0];
    const float* feat    = (const float*)d_in[1];
    const int*   fps     = (const int*)  d_in[2];
    const int*   knn     = (const int*)  d_in[3];
    const float* mlp1_w1 = (const float*)d_in[s + 0];
    const float* mlp1_b1 = (const float*)d_in[s + 1];
    const float* mlp1_w2 = (const float*)d_in[s + 2];
    const float* mlp1_b2 = (const float*)d_in[s + 3];
    const float* mlp2_w1 = (const float*)d_in[s + 4];
    const float* mlp2_b1 = (const float*)d_in[s + 5];
    const float* mlp2_w2 = (const float*)d_in[s + 6];
    const float* mlp2_b2 = (const float*)d_in[s + 7];
    const float* wq      = (const float*)d_in[s + 8];
    const float* wk      = (const float*)d_in[s + 9];
    const float* wv      = (const float*)d_in[s + 10];
    const float* wo      = (const float*)d_in[s + 11];
    const float* bo      = (const float*)d_in[s + 12];
    const float* ln_g    = (const float*)d_in[s + 13];
    const float* ln_b    = (const float*)d_in[s + 14];
    const float* td_w    = (const float*)d_in[s + 15];
    const float* td_b    = (const float*)d_in[s + 16];
    const float* bn_g    = (const float*)d_in[s + 17];
    const float* bn_b    = (const float*)d_in[s + 18];
    const float* bn_mean = (const float*)d_in[s + 19];
    const float* bn_var  = (const float*)d_in[s + 20];

    float *h1, *h2, *hpos, *hgeo, *qb, *kb, *vb, *sb, *pre, *fb, *g512, *wt;
    cudaGetSymbolAddress((void**)&h1,   d_h1);
    cudaGetSymbolAddress((void**)&h2,   d_h2);
    cudaGetSymbolAddress((void**)&hpos, d_hpos);
    cudaGetSymbolAddress((void**)&hgeo, d_hgeo);
    cudaGetSymbolAddress((void**)&qb,   d_q);
    cudaGetSymbolAddress((void**)&kb,   d_k);
    cudaGetSymbolAddress((void**)&vb,   d_v);
    cudaGetSymbolAddress((void**)&sb,   d_s);
    cudaGetSymbolAddress((void**)&pre,  d_pre);
    cudaGetSymbolAddress((void**)&fb,   d_f);
    cudaGetSymbolAddress((void**)&g512, d_g512);
    cudaGetSymbolAddress((void**)&wt,   d_wt);

    cudaFuncSetAttribute(tc_gemm,
                         cudaFuncAttributeMaxDynamicSharedMemorySize, TC_SMEM_TOTAL);
    cudaFuncSetAttribute(attn_kernel<16>,
                         cudaFuncAttributeMaxDynamicSharedMemorySize, ATTN_SMEM);
    cudaFuncSetAttribute(attn_kernel<64>,
                         cudaFuncAttributeMaxDynamicSharedMemorySize, ATTN_SMEM);

    transpose_all<<<dim3(8, 8, 14), 256>>>(mlp1_w2, mlp2_w2, wq, wk, wv, wo, td_w, wt);

    const dim3 gemmBlk(512);
    const dim3 grid256(2, RTOT / 256);   // Nout=256: 512 CTAs
    const dim3 grid512(4, RTOT / 256);   // Nout=512: 1024 CTAs

    for (int blk = 0; blk < 2; blk++) {
        const int cs = (blk == 0) ? 16 : 64;
        const int i  = blk;
        const float* fin = (blk == 0) ? feat : fb;
        const size_t bOff = (size_t)i * 256;
        float* Wt0 = wt + (size_t)(i * 6) * SLOT;

        geom_hidden_kernel<<<RTOT / cs, 256>>>(
            pos, mlp1_w1 + (size_t)i * 4 * 256, mlp1_b1 + bOff,
            mlp2_w1 + (size_t)i * 6 * 256, mlp2_b1 + bOff, h1, h2, cs);

        tc_gemm<<<grid256, gemmBlk, TC_SMEM_TOTAL>>>(h1, Wt0 + 0 * SLOT, mlp1_b2 + bOff, fin,
            hpos, nullptr, DIM, 0, 1.f, nullptr, nullptr, nullptr, nullptr);
        tc_gemm<<<grid256, gemmBlk, TC_SMEM_TOTAL>>>(h2, Wt0 + 1 * SLOT, mlp2_b2 + bOff, fin,
            hgeo, nullptr, DIM, 0, 1.f, nullptr, nullptr, nullptr, nullptr);
        tc_gemm<<<grid512, gemmBlk, TC_SMEM_TOTAL>>>(hgeo, Wt0 + 2 * SLOT, nullptr, feat,
            qb, kb, DOUT, 4, 1.f / 16.f, nullptr, nullptr, nullptr, nullptr);
        tc_gemm<<<grid256, gemmBlk, TC_SMEM_TOTAL>>>(hpos, Wt0 + 4 * SLOT, nullptr, feat,
            vb, nullptr, DIM, 2, 1.f, nullptr, nullptr, nullptr, nullptr);

        if (cs == 16)
            attn_kernel<16><<<RTOT / 64, 256, ATTN_SMEM>>>(qb, kb, vb, sb);
        else
            attn_kernel<64><<<RTOT / 64, 256, ATTN_SMEM>>>(qb, kb, vb, sb);

        tc_gemm<<<grid256, gemmBlk, TC_SMEM_TOTAL>>>(sb, Wt0 + 5 * SLOT, bo + bOff, hpos,
            pre, nullptr, DIM, 0, 1.f, nullptr, nullptr, nullptr, nullptr);

        ln_kernel<<<RTOT / 8, 256>>>(pre, ln_g + bOff, ln_b + bOff, fb);
    }

    tc_gemm<<<grid512, gemmBlk, TC_SMEM_TOTAL>>>(fb, wt + 12 * SLOT, td_b, feat,
        g512, nullptr, DOUT, 3, 1.f, bn_g, bn_b, bn_mean, bn_var);

    float* outp = (float*)d_out;
    posds_kernel<<<(BATCH * MPTS + 255) / 256, 256>>>(pos, fps, outp);
    knn_max_kernel<<<BATCH * MPTS, 128>>>(g512, knn, outp + BATCH * MPTS * 3);
}

// round 8
// speedup vs baseline: 3.1370x; 1.5309x over previous
#include <cuda_runtime.h>
#include <cuda_bf16.h>
#include <math.h>
#include <stdint.h>

// Problem constants
#define BATCH 8
#define NPTS  8192
#define DIM   256
#define DOUT  512
#define MPTS  2048
#define KNN   16
#define RTOT  (BATCH * NPTS)   // 65536 rows
#define EPS   1e-5f

// ---------------------------------------------------------------------------
// Scratch
// ---------------------------------------------------------------------------
__device__ __align__(128) float d_h1  [(size_t)RTOT * DIM];
__device__ __align__(128) float d_h2  [(size_t)RTOT * DIM];
__device__ __align__(128) float d_hpos[(size_t)RTOT * DIM];
__device__ __align__(128) float d_hgeo[(size_t)RTOT * DIM];
__device__ __align__(128) float d_q   [(size_t)RTOT * DIM];
__device__ __align__(128) float d_k   [(size_t)RTOT * DIM];
__device__ __align__(128) float d_v   [(size_t)RTOT * DIM];
__device__ __align__(128) float d_s   [(size_t)RTOT * DIM];
__device__ __align__(128) float d_pre [(size_t)RTOT * DIM];
__device__ __align__(128) float d_f   [(size_t)RTOT * DIM];
__device__ __align__(128) float d_g512[(size_t)RTOT * DOUT];
__device__ __align__(128) float d_wt  [14 * 256 * 256];

#define SLOT (256 * 256)

// ---------------------------------------------------------------------------
// helpers
// ---------------------------------------------------------------------------
__device__ __forceinline__ float f2tf32_rn(float v) {
    uint32_t u;
    asm("cvt.rna.tf32.f32 %0, %1;" : "=r"(u) : "f"(v));
    return __uint_as_float(u);
}

__device__ __forceinline__ void mma_tf32(float* c, const uint32_t* a, const uint32_t* b) {
    asm volatile(
        "mma.sync.aligned.m16n8k8.row.col.f32.tf32.tf32.f32 "
        "{%0,%1,%2,%3}, {%4,%5,%6,%7}, {%8,%9}, {%0,%1,%2,%3};"
        : "+f"(c[0]), "+f"(c[1]), "+f"(c[2]), "+f"(c[3])
        : "r"(a[0]), "r"(a[1]), "r"(a[2]), "r"(a[3]), "r"(b[0]), "r"(b[1]));
}

__device__ __forceinline__ uint32_t smem_u32(const void* p) {
    uint32_t a;
    asm("{ .reg .u64 t; cvta.to.shared.u64 t, %1; cvt.u32.u64 %0, t; }" : "=r"(a) : "l"(p));
    return a;
}

#define CP_ASYNC16(dst, src) \
    asm volatile("cp.async.cg.shared.global [%0], [%1], 16;" :: "r"(dst), "l"(src))
#define CP_COMMIT() asm volatile("cp.async.commit_group;")
template<int N> __device__ __forceinline__ void cp_wait() {
    asm volatile("cp.async.wait_group %0;" :: "n"(N));
}

#define LDSM_X4(r, addr) \
    asm volatile("ldmatrix.sync.aligned.m8n8.x4.shared.b16 {%0,%1,%2,%3}, [%4];" \
        : "=r"((r)[0]), "=r"((r)[1]), "=r"((r)[2]), "=r"((r)[3]) : "r"(addr))
#define LDSM_X2(r, addr) \
    asm volatile("ldmatrix.sync.aligned.m8n8.x2.shared.b16 {%0,%1}, [%2];" \
        : "=r"((r)[0]), "=r"((r)[1]) : "r"(addr))

// ---------------------------------------------------------------------------
// Batched weight transpose (rounded to tf32-rn at write)
// ---------------------------------------------------------------------------
__global__ __launch_bounds__(256) void transpose_all(
    const float* __restrict__ m1w2, const float* __restrict__ m2w2,
    const float* __restrict__ wq, const float* __restrict__ wk,
    const float* __restrict__ wv, const float* __restrict__ wo,
    const float* __restrict__ td, float* __restrict__ wt)
{
    __shared__ float t[32][33];
    const int z = blockIdx.z;
    const float* src;
    int srcN = 256, colOff = 0;
    float* dst;
    if (z < 12) {
        const int i = z / 6, j = z % 6;
        const size_t off = (size_t)i * SLOT;
        switch (j) {
            case 0: src = m1w2 + off; break;
            case 1: src = m2w2 + off; break;
            case 2: src = wq   + off; break;
            case 3: src = wk   + off; break;
            case 4: src = wv   + off; break;
            default: src = wo  + off; break;
        }
        dst = wt + (size_t)(i * 6 + j) * SLOT;
    } else {
        src = td; srcN = 512; colOff = (z - 12) * 256;
        dst = wt + (size_t)(12 + (z - 12)) * SLOT;
    }

    const int bx = blockIdx.x * 32;
    const int by = blockIdx.y * 32;
    const int tx = threadIdx.x & 31, ty = threadIdx.x >> 5;
#pragma unroll
    for (int i = ty; i < 32; i += 8)
        t[i][tx] = src[(size_t)(by + i) * srcN + colOff + bx + tx];
    __syncthreads();
#pragma unroll
    for (int i = ty; i < 32; i += 8)
        dst[(size_t)(bx + i) * 256 + by + tx] = f2tf32_rn(t[tx][i]);
}

// ---------------------------------------------------------------------------
// tf32 mma.sync GEMM, cp.async + ldmatrix.
// CTA tile 128x128, 256 threads (8 warps, 2x4), warp tile 64x32.
// K chunks of 32 floats, 3-stage ring (32KB/stage), 2 CTAs/SM.
// smem layout: plain row-major 32-float rows, 16B units XOR-swizzled by row&7.
// modes: 0 = +bias[c]+Add[r,c]  1 = *scale  2 = none  3 = relu(bn(acc+bias))
//        4 = dual output: col<256 -> C (q, *scale), col>=256 -> C2 (k)
// ---------------------------------------------------------------------------
#define STG_BYTES 32768                 // A 16KB + B 16KB
#define TC_SMEM_TOTAL (3 * STG_BYTES)   // 96KB

__global__ void __launch_bounds__(256, 2) tc_gemm(
    const float* __restrict__ A, const float* __restrict__ Wt,
    const float* __restrict__ bias, const float* __restrict__ Add,
    float* __restrict__ C, float* __restrict__ C2,
    int Nout, int mode, float scale,
    const float* __restrict__ bn_g, const float* __restrict__ bn_b,
    const float* __restrict__ bn_mean, const float* __restrict__ bn_var)
{
    extern __shared__ char smem[];
    const uint32_t sbase = smem_u32(smem);
    const int tid  = threadIdx.x;
    const int lane = tid & 31;
    const int wid  = tid >> 5;
    const int wr   = wid >> 2;       // 0..1 -> 64-row slab
    const int wc   = wid & 3;        // 0..3 -> 32-col slab

    const int blockRow = blockIdx.y * 128;
    const int blockCol = blockIdx.x * 128;

    const float* Abase = A  + (size_t)blockRow * 256;
    const float* Bbase = Wt + (size_t)blockCol * 256;

    // ---- cp.async loader: 4 16B per thread for A, 4 for B per chunk ----
    int rowL[4], qL[4];
    uint32_t offL[4];
#pragma unroll
    for (int i = 0; i < 4; i++) {
        const int idx = tid + i * 256;
        rowL[i] = idx >> 3;                 // 0..127
        qL[i]   = idx & 7;                  // 16B unit within row
        offL[i] = (uint32_t)rowL[i] * 128u + (uint32_t)((qL[i] ^ (rowL[i] & 7)) * 16);
    }

    auto issue_chunk = [&](int c, int s) {
        const int k0 = c * 32;
        const uint32_t ab = sbase + (uint32_t)s * STG_BYTES;
        const uint32_t bb = ab + 16384u;
#pragma unroll
        for (int i = 0; i < 4; i++)
            CP_ASYNC16(ab + offL[i], Abase + (size_t)rowL[i] * 256 + k0 + qL[i] * 4);
#pragma unroll
        for (int i = 0; i < 4; i++)
            CP_ASYNC16(bb + offL[i], Bbase + (size_t)rowL[i] * 256 + k0 + qL[i] * 4);
        CP_COMMIT();
    };

    // ---- ldmatrix addressing ----
    const int l7  = lane & 7;
    const int hA  = lane >> 4;               // A: T01/T11 half selector
    const int hB  = (lane >> 3) & 1;         // B: S1 half selector
    uint32_t aOff[4], bOff[4];
#pragma unroll
    for (int t = 0; t < 4; t++) {
        const int rA = wr * 64 + t * 16 + ((lane >> 3) & 1) * 8 + l7;
        aOff[t] = (uint32_t)rA * 128u;
        const int rB = wc * 32 + t * 8 + l7;
        bOff[t] = (uint32_t)rB * 128u;
    }

    float acc[4][4][4];
#pragma unroll
    for (int i = 0; i < 4; i++)
#pragma unroll
        for (int j = 0; j < 4; j++)
#pragma unroll
            for (int e = 0; e < 4; e++) acc[i][j][e] = 0.f;

    auto compute = [&](int s) {
        const uint32_t sA = sbase + (uint32_t)s * STG_BYTES;
        const uint32_t sB = sA + 16384u;
#pragma unroll
        for (int kt = 0; kt < 4; kt++) {
            const uint32_t qa = (uint32_t)((((kt << 1) + hA) ^ l7) << 4);
            const uint32_t qb = (uint32_t)((((kt << 1) + hB) ^ l7) << 4);
            uint32_t aF[4][4], bF[4][2];
#pragma unroll
            for (int rt4 = 0; rt4 < 4; rt4++)
                LDSM_X4(aF[rt4], sA + aOff[rt4] + qa);
#pragma unroll
            for (int nt4 = 0; nt4 < 4; nt4++)
                LDSM_X2(bF[nt4], sB + bOff[nt4] + qb);
#pragma unroll
            for (int rt4 = 0; rt4 < 4; rt4++)
#pragma unroll
                for (int nt4 = 0; nt4 < 4; nt4++)
                    mma_tf32(acc[rt4][nt4], aF[rt4], bF[nt4]);
        }
    };

    issue_chunk(0, 0);
    issue_chunk(1, 1);
#pragma unroll
    for (int c = 0; c < 8; c++) {
        if (c == 7) cp_wait<0>(); else cp_wait<1>();
        __syncthreads();
        if (c + 2 < 8) issue_chunk(c + 2, (c + 2) % 3);
        compute(c % 3);
    }

    // epilogue
    const int g   = lane >> 2;
    const int tig = lane & 3;
#pragma unroll
    for (int rt4 = 0; rt4 < 4; rt4++) {
#pragma unroll
        for (int half = 0; half < 2; half++) {
            const int row = blockRow + wr * 64 + rt4 * 16 + g + half * 8;
            float* Crow = C + (size_t)row * Nout;
            const float* Arow = Add + (size_t)row * Nout;
#pragma unroll
            for (int nt4 = 0; nt4 < 4; nt4++) {
                const int col = blockCol + wc * 32 + nt4 * 8 + tig * 2;
                float v0 = acc[rt4][nt4][half * 2 + 0];
                float v1 = acc[rt4][nt4][half * 2 + 1];
                float2 out;
                if (mode == 0) {
                    out.x = v0 + bias[col]     + Arow[col];
                    out.y = v1 + bias[col + 1] + Arow[col + 1];
                    *(float2*)(Crow + col) = out;
                } else if (mode == 1) {
                    out.x = v0 * scale; out.y = v1 * scale;
                    *(float2*)(Crow + col) = out;
                } else if (mode == 2) {
                    out.x = v0; out.y = v1;
                    *(float2*)(Crow + col) = out;
                } else if (mode == 3) {
                    float t0 = (v0 + bias[col] - bn_mean[col]) *
                               rsqrtf(bn_var[col] + EPS) * bn_g[col] + bn_b[col];
                    float t1 = (v1 + bias[col + 1] - bn_mean[col + 1]) *
                               rsqrtf(bn_var[col + 1] + EPS) * bn_g[col + 1] + bn_b[col + 1];
                    out.x = fmaxf(t0, 0.f); out.y = fmaxf(t1, 0.f);
                    *(float2*)(Crow + col) = out;
                } else {  // mode 4: dual output q/k
                    if (col < 256) {
                        out.x = v0 * scale; out.y = v1 * scale;
                        *(float2*)(C + (size_t)row * 256 + col) = out;
                    } else {
                        out.x = v0; out.y = v1;
                        *(float2*)(C2 + (size_t)row * 256 + (col - 256)) = out;
                    }
                }
            }
        }
    }
}

// ---------------------------------------------------------------------------
// Per-chunk geometry + first MLP layers (4->256 and 6->256, relu)
// ---------------------------------------------------------------------------
__global__ __launch_bounds__(256) void geom_hidden_kernel(
    const float* __restrict__ pos,
    const float* __restrict__ w1, const float* __restrict__ b1,
    const float* __restrict__ w2, const float* __restrict__ b2,
    float* __restrict__ H1, float* __restrict__ H2, int cs)
{
    __shared__ float ps[64][3];
    __shared__ float lp[64][4];
    __shared__ float cog[3], avg[3];

    const int tid = threadIdx.x;
    const size_t gp = (size_t)blockIdx.x * cs;

    if (tid < cs) {
        ps[tid][0] = pos[(gp + tid) * 3 + 0];
        ps[tid][1] = pos[(gp + tid) * 3 + 1];
        ps[tid][2] = pos[(gp + tid) * 3 + 2];
    }
    __syncthreads();
    if (tid < 3) {
        float s = 0.f;
        for (int p = 0; p < cs; p++) s += ps[p][tid];
        cog[tid] = s / (float)cs;
    }
    __syncthreads();
    if (tid < cs) {
        float x = ps[tid][0] - cog[0];
        float y = ps[tid][1] - cog[1];
        float z = ps[tid][2] - cog[2];
        lp[tid][0] = x; lp[tid][1] = y; lp[tid][2] = z;
        lp[tid][3] = sqrtf(x * x + y * y + z * z);
    }
    __syncthreads();
    if (tid < 3) {
        float s = 0.f;
        for (int p = 0; p < cs; p++) s += lp[p][tid];
        avg[tid] = s / (float)cs;
    }
    __syncthreads();

    const int j = tid;
    float w1c[4], w2c[6];
#pragma unroll
    for (int t = 0; t < 4; t++) w1c[t] = w1[t * 256 + j];
#pragma unroll
    for (int t = 0; t < 6; t++) w2c[t] = w2[t * 256 + j];
    const float b1v = b1[j], b2v = b2[j];
    const float a0 = avg[0], a1 = avg[1], a2 = avg[2];

    for (int p = 0; p < cs; p++) {
        float x = lp[p][0], y = lp[p][1], z = lp[p][2], n = lp[p][3];
        float h1 = fmaxf(b1v + x * w1c[0] + y * w1c[1] + z * w1c[2] + n * w1c[3], 0.f);
        float h2 = fmaxf(b2v + a0 * w2c[0] + a1 * w2c[1] + a2 * w2c[2] +
                               x * w2c[3] + y * w2c[4] + z * w2c[5], 0.f);
        H1[(gp + p) * 256 + j] = f2tf32_rn(h1);
        H2[(gp + p) * 256 + j] = f2tf32_rn(h2);
    }
}

// ---------------------------------------------------------------------------
// Register-blocked chunk attention. CTA = 64 points.
// ---------------------------------------------------------------------------
#define SQ 257
#define SVP 264
#define ATTN_SMEM ((2 * 64 * SQ + 4096) * 4)

template<int CS>
__global__ __launch_bounds__(256) void attn_kernel(
    const float* __restrict__ Q, const float* __restrict__ Kf,
    const float* __restrict__ V, float* __restrict__ Out)
{
    extern __shared__ float sm[];
    float* Qs = sm;
    float* Ks = sm + 64 * SQ;
    float* P  = sm + 2 * 64 * SQ;
    float* Vs = sm;

    const int tid = threadIdx.x;
    const size_t base = (size_t)blockIdx.x * 64 * 256;

    for (int idx = tid; idx < 64 * 256; idx += 256) {
        int p = idx >> 8, t = idx & 255;
        Qs[p * SQ + t] = Q[base + idx];
        Ks[p * SQ + t] = Kf[base + idx];
    }
    __syncthreads();

    if (CS == 64) {
        const int i0 = (tid >> 4) * 4;
        const int j0 = (tid & 15) * 4;
        float acc[4][4] = {};
        for (int t = 0; t < 256; t++) {
            float qv[4], kv[4];
#pragma unroll
            for (int e = 0; e < 4; e++) qv[e] = Qs[(i0 + e) * SQ + t];
#pragma unroll
            for (int f = 0; f < 4; f++) kv[f] = Ks[(j0 + f) * SQ + t];
#pragma unroll
            for (int e = 0; e < 4; e++)
#pragma unroll
                for (int f = 0; f < 4; f++) acc[e][f] += qv[e] * kv[f];
        }
#pragma unroll
        for (int e = 0; e < 4; e++)
#pragma unroll
            for (int f = 0; f < 4; f++) P[(i0 + e) * 64 + j0 + f] = acc[e][f];
    } else {
        const int ch = tid >> 6;
        const int r  = (tid >> 2) & 15;
        const int j0 = (tid & 3) * 4;
        const int gi = ch * 16 + r;
        const int gj = ch * 16 + j0;
        float acc[4] = {};
        for (int t = 0; t < 256; t++) {
            float qv = Qs[gi * SQ + t];
#pragma unroll
            for (int f = 0; f < 4; f++) acc[f] += qv * Ks[(gj + f) * SQ + t];
        }
#pragma unroll
        for (int f = 0; f < 4; f++) P[ch * 256 + r * 16 + j0 + f] = acc[f];
    }
    __syncthreads();

    if (CS == 64) {
        const int warp = tid >> 5, lane = tid & 31;
        for (int i = warp; i < 64; i += 8) {
            float* row = P + i * 64;
            float a = row[lane], b = row[lane + 32];
            float mx = fmaxf(a, b);
#pragma unroll
            for (int o = 16; o; o >>= 1) mx = fmaxf(mx, __shfl_xor_sync(0xFFFFFFFFu, mx, o));
            float ea = __expf(a - mx), eb = __expf(b - mx);
            float sum = ea + eb;
#pragma unroll
            for (int o = 16; o; o >>= 1) sum += __shfl_xor_sync(0xFFFFFFFFu, sum, o);
            float inv = 1.f / sum;
            row[lane] = ea * inv;
            row[lane + 32] = eb * inv;
        }
    } else {
        if (tid < 64) {
            float* row = P + (tid >> 4) * 256 + (tid & 15) * 16;
            float mx = -1e30f;
#pragma unroll
            for (int j = 0; j < 16; j++) mx = fmaxf(mx, row[j]);
            float sum = 0.f;
            float e[16];
#pragma unroll
            for (int j = 0; j < 16; j++) { e[j] = __expf(row[j] - mx); sum += e[j]; }
            float inv = 1.f / sum;
#pragma unroll
            for (int j = 0; j < 16; j++) row[j] = e[j] * inv;
        }
    }
    __syncthreads();

    for (int idx = tid; idx < 64 * 256; idx += 256) {
        int p = idx >> 8, t = idx & 255;
        Vs[p * SVP + t] = V[base + idx];
    }
    __syncthreads();

    {
        const int i0 = (tid >> 4) * 4;
        const int tq = tid & 15;
        const int cb = i0 & ~(CS - 1);
        float acc[4][16] = {};
        for (int j = 0; j < CS; j++) {
            float pv[4];
            if (CS == 64) {
#pragma unroll
                for (int e = 0; e < 4; e++) pv[e] = P[(i0 + e) * 64 + j];
            } else {
                const int chk = i0 >> 4;
#pragma unroll
                for (int e = 0; e < 4; e++) pv[e] = P[chk * 256 + (i0 + e - cb) * 16 + j];
            }
            const float* vr = Vs + (cb + j) * SVP + tq;
            float vv[16];
#pragma unroll
            for (int m = 0; m < 16; m++) vv[m] = vr[m * 16];
#pragma unroll
            for (int e = 0; e < 4; e++)
#pragma unroll
                for (int m = 0; m < 16; m++) acc[e][m] += pv[e] * vv[m];
        }
#pragma unroll
        for (int e = 0; e < 4; e++)
#pragma unroll
            for (int m = 0; m < 16; m++)
                Out[base + (size_t)(i0 + e) * 256 + tq + m * 16] = f2tf32_rn(acc[e][m]);
    }
}

// ---------------------------------------------------------------------------
// LayerNorm over last dim (256): warp-per-row, 8 rows per CTA.
// ---------------------------------------------------------------------------
__global__ __launch_bounds__(256) void ln_kernel(
    const float* __restrict__ X, const float* __restrict__ g,
    const float* __restrict__ b, float* __restrict__ Y)
{
    const int warp = threadIdx.x >> 5, lane = threadIdx.x & 31;
    const size_t row = (size_t)blockIdx.x * 8 + warp;
    const float4* xr = (const float4*)(X + row * 256);
    float4 x0 = xr[lane], x1 = xr[lane + 32];

    float s = x0.x + x0.y + x0.z + x0.w + x1.x + x1.y + x1.z + x1.w;
#pragma unroll
    for (int o = 16; o; o >>= 1) s += __shfl_xor_sync(0xFFFFFFFFu, s, o);
    const float mu = s * (1.f / 256.f);

    float v = 0.f;
    float d0x = x0.x - mu, d0y = x0.y - mu, d0z = x0.z - mu, d0w = x0.w - mu;
    float d1x = x1.x - mu, d1y = x1.y - mu, d1z = x1.z - mu, d1w = x1.w - mu;
    v = d0x*d0x + d0y*d0y + d0z*d0z + d0w*d0w + d1x*d1x + d1y*d1y + d1z*d1z + d1w*d1w;
#pragma unroll
    for (int o = 16; o; o >>= 1) v += __shfl_xor_sync(0xFFFFFFFFu, v, o);
    const float inv = rsqrtf(v * (1.f / 256.f) + EPS);

    const float4 g0 = *(const float4*)&g[lane * 4];
    const float4 g1 = *(const float4*)&g[(lane + 32) * 4];
    const float4 b0 = *(const float4*)&b[lane * 4];
    const float4 b1 = *(const float4*)&b[(lane + 32) * 4];
    float4 y0, y1;
    y0.x = d0x * inv * g0.x + b0.x; y0.y = d0y * inv * g0.y + b0.y;
    y0.z = d0z * inv * g0.z + b0.z; y0.w = d0w * inv * g0.w + b0.w;
    y1.x = d1x * inv * g1.x + b1.x; y1.y = d1y * inv * g1.y + b1.y;
    y1.z = d1z * inv * g1.z + b1.z; y1.w = d1w * inv * g1.w + b1.w;
    float4* yr = (float4*)(Y + row * 256);
    yr[lane] = y0; yr[lane + 32] = y1;
}

// ---------------------------------------------------------------------------
// kNN gather + channel max (float4), pos downsample
// ---------------------------------------------------------------------------
__global__ __launch_bounds__(128) void knn_max_kernel(
    const float* __restrict__ G, const int* __restrict__ knn,
    float* __restrict__ out)
{
    const int bm = blockIdx.x;
    const int b  = bm / MPTS;
    const int tid = threadIdx.x;
    __shared__ int idxs[KNN];
    if (tid < KNN) idxs[tid] = knn[(size_t)bm * KNN + tid];
    __syncthreads();
    float4 m = make_float4(-3.0e38f, -3.0e38f, -3.0e38f, -3.0e38f);
#pragma unroll
    for (int k = 0; k < KNN; k++) {
        const float4 gg = *(const float4*)&G[((size_t)b * NPTS + idxs[k]) * DOUT + tid * 4];
        m.x = fmaxf(m.x, gg.x); m.y = fmaxf(m.y, gg.y);
        m.z = fmaxf(m.z, gg.z); m.w = fmaxf(m.w, gg.w);
    }
    *(float4*)&out[(size_t)bm * DOUT + tid * 4] = m;
}

__global__ void posds_kernel(const float* __restrict__ pos,
                             const int* __restrict__ fps,
                             float* __restrict__ out)
{
    int p = blockIdx.x * blockDim.x + threadIdx.x;
    if (p < BATCH * MPTS) {
        int b = p / MPTS;
        int n = fps[p];
        size_t src = ((size_t)b * NPTS + n) * 3;
        out[p * 3 + 0] = pos[src + 0];
        out[p * 3 + 1] = pos[src + 1];
        out[p * 3 + 2] = pos[src + 2];
    }
}

// ---------------------------------------------------------------------------
// Orchestration
// ---------------------------------------------------------------------------
extern "C" void kernel_launch(void* const* d_in, const int* in_sizes, int n_in,
                              void* d_out, int out_size)
{
    const int s = (n_in >= 27) ? 6 : 4;

    const float* pos     = (const float*)d_in[0];
    const float* feat    = (const float*)d_in[1];
    const int*   fps     = (const int*)  d_in[2];
    const int*   knn     = (const int*)  d_in[3];
    const float* mlp1_w1 = (const float*)d_in[s + 0];
    const float* mlp1_b1 = (const float*)d_in[s + 1];
    const float* mlp1_w2 = (const float*)d_in[s + 2];
    const float* mlp1_b2 = (const float*)d_in[s + 3];
    const float* mlp2_w1 = (const float*)d_in[s + 4];
    const float* mlp2_b1 = (const float*)d_in[s + 5];
    const float* mlp2_w2 = (const float*)d_in[s + 6];
    const float* mlp2_b2 = (const float*)d_in[s + 7];
    const float* wq      = (const float*)d_in[s + 8];
    const float* wk      = (const float*)d_in[s + 9];
    const float* wv      = (const float*)d_in[s + 10];
    const float* wo      = (const float*)d_in[s + 11];
    const float* bo      = (const float*)d_in[s + 12];
    const float* ln_g    = (const float*)d_in[s + 13];
    const float* ln_b    = (const float*)d_in[s + 14];
    const float* td_w    = (const float*)d_in[s + 15];
    const float* td_b    = (const float*)d_in[s + 16];
    const float* bn_g    = (const float*)d_in[s + 17];
    const float* bn_b    = (const float*)d_in[s + 18];
    const float* bn_mean = (const float*)d_in[s + 19];
    const float* bn_var  = (const float*)d_in[s + 20];

    float *h1, *h2, *hpos, *hgeo, *qb, *kb, *vb, *sb, *pre, *fb, *g512, *wt;
    cudaGetSymbolAddress((void**)&h1,   d_h1);
    cudaGetSymbolAddress((void**)&h2,   d_h2);
    cudaGetSymbolAddress((void**)&hpos, d_hpos);
    cudaGetSymbolAddress((void**)&hgeo, d_hgeo);
    cudaGetSymbolAddress((void**)&qb,   d_q);
    cudaGetSymbolAddress((void**)&kb,   d_k);
    cudaGetSymbolAddress((void**)&vb,   d_v);
    cudaGetSymbolAddress((void**)&sb,   d_s);
    cudaGetSymbolAddress((void**)&pre,  d_pre);
    cudaGetSymbolAddress((void**)&fb,   d_f);
    cudaGetSymbolAddress((void**)&g512, d_g512);
    cudaGetSymbolAddress((void**)&wt,   d_wt);

    cudaFuncSetAttribute(tc_gemm,
                         cudaFuncAttributeMaxDynamicSharedMemorySize, TC_SMEM_TOTAL);
    cudaFuncSetAttribute(attn_kernel<16>,
                         cudaFuncAttributeMaxDynamicSharedMemorySize, ATTN_SMEM);
    cudaFuncSetAttribute(attn_kernel<64>,
                         cudaFuncAttributeMaxDynamicSharedMemorySize, ATTN_SMEM);

    transpose_all<<<dim3(8, 8, 14), 256>>>(mlp1_w2, mlp2_w2, wq, wk, wv, wo, td_w, wt);

    const dim3 gemmBlk(256);
    const dim3 grid256(2, RTOT / 128);   // Nout=256: 1024 CTAs
    const dim3 grid512(4, RTOT / 128);   // Nout=512: 2048 CTAs

    for (int blk = 0; blk < 2; blk++) {
        const int cs = (blk == 0) ? 16 : 64;
        const int i  = blk;
        const float* fin = (blk == 0) ? feat : fb;
        const size_t bOff = (size_t)i * 256;
        float* Wt0 = wt + (size_t)(i * 6) * SLOT;

        geom_hidden_kernel<<<RTOT / cs, 256>>>(
            pos, mlp1_w1 + (size_t)i * 4 * 256, mlp1_b1 + bOff,
            mlp2_w1 + (size_t)i * 6 * 256, mlp2_b1 + bOff, h1, h2, cs);

        tc_gemm<<<grid256, gemmBlk, TC_SMEM_TOTAL>>>(h1, Wt0 + 0 * SLOT, mlp1_b2 + bOff, fin,
            hpos, nullptr, DIM, 0, 1.f, nullptr, nullptr, nullptr, nullptr);
        tc_gemm<<<grid256, gemmBlk, TC_SMEM_TOTAL>>>(h2, Wt0 + 1 * SLOT, mlp2_b2 + bOff, fin,
            hgeo, nullptr, DIM, 0, 1.f, nullptr, nullptr, nullptr, nullptr);
        tc_gemm<<<grid512, gemmBlk, TC_SMEM_TOTAL>>>(hgeo, Wt0 + 2 * SLOT, nullptr, feat,
            qb, kb, DOUT, 4, 1.f / 16.f, nullptr, nullptr, nullptr, nullptr);
        tc_gemm<<<grid256, gemmBlk, TC_SMEM_TOTAL>>>(hpos, Wt0 + 4 * SLOT, nullptr, feat,
            vb, nullptr, DIM, 2, 1.f, nullptr, nullptr, nullptr, nullptr);

        if (cs == 16)
            attn_kernel<16><<<RTOT / 64, 256, ATTN_SMEM>>>(qb, kb, vb, sb);
        else
            attn_kernel<64><<<RTOT / 64, 256, ATTN_SMEM>>>(qb, kb, vb, sb);

        tc_gemm<<<grid256, gemmBlk, TC_SMEM_TOTAL>>>(sb, Wt0 + 5 * SLOT, bo + bOff, hpos,
            pre, nullptr, DIM, 0, 1.f, nullptr, nullptr, nullptr, nullptr);

        ln_kernel<<<RTOT / 8, 256>>>(pre, ln_g + bOff, ln_b + bOff, fb);
    }

    tc_gemm<<<grid512, gemmBlk, TC_SMEM_TOTAL>>>(fb, wt + 12 * SLOT, td_b, feat,
        g512, nullptr, DOUT, 3, 1.f, bn_g, bn_b, bn_mean, bn_var);

    float* outp = (float*)d_out;
    posds_kernel<<<(BATCH * MPTS + 255) / 256, 256>>>(pos, fps, outp);
    knn_max_kernel<<<BATCH * MPTS, 128>>>(g512, knn, outp + BATCH * MPTS * 3);
}